// round 1
// baseline (speedup 1.0000x reference)
#include <cuda_runtime.h>

#define NB 8
#define NS 2048
#define ND 1024

// ---------------- scratch (device globals; no allocs allowed) ----------------
__device__ float g_q[NB * NS * ND];
__device__ float g_k[NB * NS * ND];
__device__ float g_v[NB * NS * ND];
__device__ float g_attn[NB * NS * ND];
__device__ float g_post[NB * NS * ND];
__device__ float g_ffn[NB * NS * ND];
__device__ float g_sc[NB * NS * NS];   // 8*2048*2048 = 33,554,432 floats

// ---------------- packed fp32x2 helpers (Blackwell FFMA2) ----------------
union F2U { unsigned long long u; float2 f; };

__device__ __forceinline__ unsigned long long ffma2(unsigned long long a,
                                                    unsigned long long b,
                                                    unsigned long long c) {
    unsigned long long d;
    asm("fma.rn.f32x2 %0, %1, %2, %3;" : "=l"(d) : "l"(a), "l"(b), "l"(c));
    return d;
}

__device__ __forceinline__ unsigned long long dup2(float a) {
    unsigned long long d;
    unsigned int u = __float_as_uint(a);
    asm("mov.b64 %0, {%1, %1};" : "=l"(d) : "r"(u));
    return d;
}

// ---------------- GEMM tiles ----------------
#define BM 128
#define BN 128
#define BK 16
#define PAD 4   // keeps 16B alignment of smem rows (132 floats = 528B)

// C[m,n] = alpha * sum_k A[m,k] * B[n,k]  (+bias, +relu, +resid), batched via z
__global__ void __launch_bounds__(256, 2)
gemm_nt(const float* __restrict__ A, const float* __restrict__ Bw,
        const float* __restrict__ bias, const float* __restrict__ resid,
        float* __restrict__ C,
        int K, int lda, int ldb, int ldc,
        long sA, long sB, long sC,
        float alpha, int relu, const int* __restrict__ lens)
{
    __shared__ float As[BK][BM + PAD];
    __shared__ float Bs[BK][BN + PAD];

    const int t  = threadIdx.x;
    const int tx = t & 15;
    const int ty = t >> 4;
    const int m0 = blockIdx.y * BM;
    const int n0 = blockIdx.x * BN;

    if (lens) {                         // skip fully-masked score tiles
        int len = lens[blockIdx.z];
        if (n0 >= len) return;
    }

    const float* Ab = A  + (long)blockIdx.z * sA;
    const float* Bb = Bw + (long)blockIdx.z * sB;
    float*       Cb = C  + (long)blockIdx.z * sC;

    unsigned long long acc[8][4];
#pragma unroll
    for (int i = 0; i < 8; i++)
#pragma unroll
        for (int j = 0; j < 4; j++) acc[i][j] = 0ull;

    const int lr = t >> 2;         // 0..63
    const int lc = (t & 3) * 4;    // 0,4,8,12

    for (int k0 = 0; k0 < K; k0 += BK) {
#pragma unroll
        for (int i = 0; i < 2; i++) {
            int r = lr + i * 64;
            float4 va = *(const float4*)(Ab + (long)(m0 + r) * lda + k0 + lc);
            As[lc + 0][r] = va.x; As[lc + 1][r] = va.y;
            As[lc + 2][r] = va.z; As[lc + 3][r] = va.w;
        }
#pragma unroll
        for (int i = 0; i < 2; i++) {
            int r = lr + i * 64;
            float4 vb = *(const float4*)(Bb + (long)(n0 + r) * ldb + k0 + lc);
            Bs[lc + 0][r] = vb.x; Bs[lc + 1][r] = vb.y;
            Bs[lc + 2][r] = vb.z; Bs[lc + 3][r] = vb.w;
        }
        __syncthreads();

#pragma unroll
        for (int k = 0; k < BK; k++) {
            float4 a0 = *(const float4*)&As[k][ty * 8];
            float4 a1 = *(const float4*)&As[k][ty * 8 + 4];
            ulonglong2 b0 = *(const ulonglong2*)&Bs[k][tx * 8];
            ulonglong2 b1 = *(const ulonglong2*)&Bs[k][tx * 8 + 4];
            unsigned long long bp[4] = { b0.x, b0.y, b1.x, b1.y };
            float av[8] = { a0.x, a0.y, a0.z, a0.w, a1.x, a1.y, a1.z, a1.w };
#pragma unroll
            for (int i = 0; i < 8; i++) {
                unsigned long long ad = dup2(av[i]);
#pragma unroll
                for (int j = 0; j < 4; j++)
                    acc[i][j] = ffma2(ad, bp[j], acc[i][j]);
            }
        }
        __syncthreads();
    }

    const int mbase = m0 + ty * 8;
    const int nbase = n0 + tx * 8;
#pragma unroll
    for (int i = 0; i < 8; i++) {
        long m = mbase + i;
#pragma unroll
        for (int h = 0; h < 2; h++) {
            F2U u0, u1;
            u0.u = acc[i][h * 2];
            u1.u = acc[i][h * 2 + 1];
            int n = nbase + h * 4;
            float4 o = make_float4(u0.f.x * alpha, u0.f.y * alpha,
                                   u1.f.x * alpha, u1.f.y * alpha);
            if (bias) {
                float4 bb = *(const float4*)(bias + n);
                o.x += bb.x; o.y += bb.y; o.z += bb.z; o.w += bb.w;
            }
            if (relu) {
                o.x = fmaxf(o.x, 0.f); o.y = fmaxf(o.y, 0.f);
                o.z = fmaxf(o.z, 0.f); o.w = fmaxf(o.w, 0.f);
            }
            if (resid) {
                float4 r4 = *(const float4*)(resid + m * ldc + n);
                o.x += r4.x; o.y += r4.y; o.z += r4.z; o.w += r4.w;
            }
            *(float4*)(Cb + m * ldc + n) = o;
        }
    }
}

// C[m,n] = sum_k A[m,k] * B[k,n]   (P @ V), batched via z, K truncated at len
__global__ void __launch_bounds__(256, 2)
gemm_nn(const float* __restrict__ A, const float* __restrict__ Bm,
        float* __restrict__ C,
        int K, int lda, int ldb, int ldc,
        long sA, long sB, long sC, const int* __restrict__ lens)
{
    __shared__ float As[BK][BM + PAD];
    __shared__ float Bs[BK][BN + PAD];

    const int t  = threadIdx.x;
    const int tx = t & 15;
    const int ty = t >> 4;
    const int m0 = blockIdx.y * BM;
    const int n0 = blockIdx.x * BN;

    int kmax = K;
    if (lens) {
        int len = lens[blockIdx.z];
        kmax = min(K, (len + BK - 1) & ~(BK - 1));
    }

    const float* Ab = A  + (long)blockIdx.z * sA;
    const float* Bb = Bm + (long)blockIdx.z * sB;
    float*       Cb = C  + (long)blockIdx.z * sC;

    unsigned long long acc[8][4];
#pragma unroll
    for (int i = 0; i < 8; i++)
#pragma unroll
        for (int j = 0; j < 4; j++) acc[i][j] = 0ull;

    const int lr = t >> 2;          // A-tile: 0..63
    const int lc = (t & 3) * 4;
    const int br = t >> 5;          // B-tile: 0..7
    const int bc = (t & 31) * 4;    // 0..124

    for (int k0 = 0; k0 < kmax; k0 += BK) {
#pragma unroll
        for (int i = 0; i < 2; i++) {
            int r = lr + i * 64;
            float4 va = *(const float4*)(Ab + (long)(m0 + r) * lda + k0 + lc);
            As[lc + 0][r] = va.x; As[lc + 1][r] = va.y;
            As[lc + 2][r] = va.z; As[lc + 3][r] = va.w;
        }
#pragma unroll
        for (int i = 0; i < 2; i++) {
            int r = br + i * 8;
            float4 vb = *(const float4*)(Bb + (long)(k0 + r) * ldb + n0 + bc);
            *(float4*)&Bs[r][bc] = vb;
        }
        __syncthreads();

#pragma unroll
        for (int k = 0; k < BK; k++) {
            float4 a0 = *(const float4*)&As[k][ty * 8];
            float4 a1 = *(const float4*)&As[k][ty * 8 + 4];
            ulonglong2 b0 = *(const ulonglong2*)&Bs[k][tx * 8];
            ulonglong2 b1 = *(const ulonglong2*)&Bs[k][tx * 8 + 4];
            unsigned long long bp[4] = { b0.x, b0.y, b1.x, b1.y };
            float av[8] = { a0.x, a0.y, a0.z, a0.w, a1.x, a1.y, a1.z, a1.w };
#pragma unroll
            for (int i = 0; i < 8; i++) {
                unsigned long long ad = dup2(av[i]);
#pragma unroll
                for (int j = 0; j < 4; j++)
                    acc[i][j] = ffma2(ad, bp[j], acc[i][j]);
            }
        }
        __syncthreads();
    }

    const int mbase = m0 + ty * 8;
    const int nbase = n0 + tx * 8;
#pragma unroll
    for (int i = 0; i < 8; i++) {
        long m = mbase + i;
#pragma unroll
        for (int h = 0; h < 2; h++) {
            F2U u0, u1;
            u0.u = acc[i][h * 2];
            u1.u = acc[i][h * 2 + 1];
            float4 o = make_float4(u0.f.x, u0.f.y, u1.f.x, u1.f.y);
            *(float4*)(Cb + m * ldc + nbase + h * 4) = o;
        }
    }
}

// ---------------- masked row softmax (in place on scores) ----------------
__global__ void softmax_rows(float* __restrict__ sc, const int* __restrict__ lens)
{
    __shared__ float red[256];
    const int t = threadIdx.x;
    const int q = blockIdx.x;
    const int b = blockIdx.y;
    float* row = sc + ((long)b * NS + q) * NS;
    const int len = lens[b];

    float m = -3.4e38f;
    for (int j = t; j < len; j += 256) m = fmaxf(m, row[j]);
    red[t] = m; __syncthreads();
    for (int s = 128; s > 0; s >>= 1) {
        if (t < s) red[t] = fmaxf(red[t], red[t + s]);
        __syncthreads();
    }
    m = red[0]; __syncthreads();

    float sum = 0.f;
    for (int j = t; j < len; j += 256) sum += __expf(row[j] - m);
    red[t] = sum; __syncthreads();
    for (int s = 128; s > 0; s >>= 1) {
        if (t < s) red[t] += red[t + s];
        __syncthreads();
    }
    const float inv = 1.0f / red[0];

    for (int j = t; j < NS; j += 256)
        row[j] = (j < len) ? __expf(row[j] - m) * inv : 0.f;
}

// ---------------- (optional residual add) + LayerNorm ----------------
__global__ void add_ln(const float* __restrict__ x, const float* __restrict__ res,
                       const float* __restrict__ g, const float* __restrict__ bt,
                       float* __restrict__ out)
{
    __shared__ float r1[256], r2[256];
    const int t = threadIdx.x;
    const long row = blockIdx.x;

    float4 v = ((const float4*)(x + row * ND))[t];
    if (res) {
        float4 w = ((const float4*)(res + row * ND))[t];
        v.x += w.x; v.y += w.y; v.z += w.z; v.w += w.w;
    }
    float s  = v.x + v.y + v.z + v.w;
    float ss = v.x * v.x + v.y * v.y + v.z * v.z + v.w * v.w;
    r1[t] = s; r2[t] = ss; __syncthreads();
    for (int k = 128; k > 0; k >>= 1) {
        if (t < k) { r1[t] += r1[t + k]; r2[t] += r2[t + k]; }
        __syncthreads();
    }
    const float mean = r1[0] * (1.0f / ND);
    const float var  = r2[0] * (1.0f / ND) - mean * mean;
    const float inv  = rsqrtf(var + 1e-5f);

    float4 gg = ((const float4*)g)[t];
    float4 bb = ((const float4*)bt)[t];
    float4 o;
    o.x = (v.x - mean) * inv * gg.x + bb.x;
    o.y = (v.y - mean) * inv * gg.y + bb.y;
    o.z = (v.z - mean) * inv * gg.z + bb.z;
    o.w = (v.w - mean) * inv * gg.w + bb.w;
    ((float4*)(out + row * ND))[t] = o;
}

// ---------------- launch ----------------
extern "C" void kernel_launch(void* const* d_in, const int* in_sizes, int n_in,
                              void* d_out, int out_size)
{
    const float* seq  = (const float*)d_in[0];
    const int*   lens = (const int*)  d_in[1];
    const float* Wq = (const float*)d_in[2];
    const float* bq = (const float*)d_in[3];
    const float* Wk = (const float*)d_in[4];
    const float* bk = (const float*)d_in[5];
    const float* Wv = (const float*)d_in[6];
    const float* bv = (const float*)d_in[7];
    const float* Wo = (const float*)d_in[8];
    const float* bo = (const float*)d_in[9];
    const float* g1 = (const float*)d_in[10];
    const float* b1 = (const float*)d_in[11];
    const float* g2 = (const float*)d_in[12];
    const float* b2 = (const float*)d_in[13];
    float* out = (float*)d_out;

    float *q, *k, *v, *attn, *post, *ffn, *sc;
    cudaGetSymbolAddress((void**)&q,    g_q);
    cudaGetSymbolAddress((void**)&k,    g_k);
    cudaGetSymbolAddress((void**)&v,    g_v);
    cudaGetSymbolAddress((void**)&attn, g_attn);
    cudaGetSymbolAddress((void**)&post, g_post);
    cudaGetSymbolAddress((void**)&ffn,  g_ffn);
    cudaGetSymbolAddress((void**)&sc,   g_sc);

    const dim3 blk(256);
    const long SD = (long)NS * ND;
    const long SS2 = (long)NS * NS;

    // Q, K, V projections: [16384,1024] = seq @ W^T + b
    dim3 gproj(ND / BN, (NB * NS) / BM, 1);
    gemm_nt<<<gproj, blk>>>(seq, Wq, bq, nullptr, q, ND, ND, ND, ND, 0, 0, 0, 1.f, 0, nullptr);
    gemm_nt<<<gproj, blk>>>(seq, Wk, bk, nullptr, k, ND, ND, ND, ND, 0, 0, 0, 1.f, 0, nullptr);
    gemm_nt<<<gproj, blk>>>(seq, Wv, bv, nullptr, v, ND, ND, ND, ND, 0, 0, 0, 1.f, 0, nullptr);

    // scores = Q @ K^T / 32, per batch; masked column-tiles skipped
    gemm_nt<<<dim3(NS / BN, NS / BM, NB), blk>>>(q, k, nullptr, nullptr, sc,
                                                 ND, ND, ND, NS, SD, SD, SS2,
                                                 1.0f / 32.0f, 0, lens);

    softmax_rows<<<dim3(NS, NB), blk>>>(sc, lens);

    // attn = P @ V, per batch, K truncated at len
    gemm_nn<<<dim3(ND / BN, NS / BM, NB), blk>>>(sc, v, attn,
                                                 NS, NS, ND, ND, SS2, SD, SD, lens);

    // post = LN(seq + attn)
    add_ln<<<NB * NS, blk>>>(attn, seq, g1, b1, post);

    // ffn = relu(post @ Wo^T + bo) + post
    gemm_nt<<<gproj, blk>>>(post, Wo, bo, post, ffn, ND, ND, ND, ND, 0, 0, 0, 1.f, 1, nullptr);

    // out = LN(ffn)
    add_ln<<<NB * NS, blk>>>(ffn, nullptr, g2, b2, out);
}

// round 4
// speedup vs baseline: 2.1321x; 2.1321x over previous
#include <cuda_runtime.h>
#include <cuda_bf16.h>
#include <cstdint>

#define NB 8
#define NS 2048
#define ND 1024

// ---------------- scratch (device globals; no allocs allowed) ----------------
__device__ __nv_bfloat16 g_seqh[NB*NS*ND], g_seql[NB*NS*ND];
__device__ __nv_bfloat16 g_wqh[ND*ND], g_wql[ND*ND];
__device__ __nv_bfloat16 g_wkh[ND*ND], g_wkl[ND*ND];
__device__ __nv_bfloat16 g_wvh[ND*ND], g_wvl[ND*ND];
__device__ __nv_bfloat16 g_woh[ND*ND], g_wol[ND*ND];
__device__ __nv_bfloat16 g_qh[NB*NS*ND], g_ql[NB*NS*ND];
__device__ __nv_bfloat16 g_kh[NB*NS*ND], g_kl[NB*NS*ND];
__device__ __nv_bfloat16 g_vth[NB*NS*ND], g_vtl[NB*NS*ND];   // V^T: [B][D][S]
__device__ __nv_bfloat16 g_sch[NB*NS*NS], g_scl[NB*NS*NS];   // split softmax P
__device__ __nv_bfloat16 g_posth[NB*NS*ND], g_postl[NB*NS*ND];
__device__ float g_sc[NB*NS*NS];
__device__ float g_attn[NB*NS*ND];
__device__ float g_post[NB*NS*ND];
__device__ float g_ffn[NB*NS*ND];

// ---------------- PTX helpers (all compute_100-legal: sm_80-era) ----------------
__device__ __forceinline__ uint32_t smem_u32(const void* p) {
    uint32_t a;
    asm("{ .reg .u64 t; cvta.to.shared.u64 t, %1; cvt.u32.u64 %0, t; }" : "=r"(a) : "l"(p));
    return a;
}

#define CP_ASYNC16(s, g) \
    asm volatile("cp.async.cg.shared.global [%0], [%1], 16;" :: "r"(s), "l"(g) : "memory")
#define CP_COMMIT() asm volatile("cp.async.commit_group;" ::: "memory")
#define CP_WAIT1()  asm volatile("cp.async.wait_group 1;" ::: "memory")

__device__ __forceinline__ void ldmx4(uint32_t r[4], uint32_t a) {
    asm volatile("ldmatrix.sync.aligned.m8n8.x4.shared.b16 {%0,%1,%2,%3}, [%4];"
        : "=r"(r[0]), "=r"(r[1]), "=r"(r[2]), "=r"(r[3]) : "r"(a));
}

__device__ __forceinline__ void mma16816(float c[4], const uint32_t a[4],
                                         uint32_t b0, uint32_t b1) {
    asm volatile("mma.sync.aligned.m16n8k16.row.col.f32.bf16.bf16.f32 "
        "{%0,%1,%2,%3}, {%4,%5,%6,%7}, {%8,%9}, {%0,%1,%2,%3};"
        : "+f"(c[0]), "+f"(c[1]), "+f"(c[2]), "+f"(c[3])
        : "r"(a[0]), "r"(a[1]), "r"(a[2]), "r"(a[3]), "r"(b0), "r"(b1));
}

__device__ __forceinline__ void splitf(float x, __nv_bfloat16& h, __nv_bfloat16& l) {
    h = __float2bfloat16(x);
    l = __float2bfloat16(x - __bfloat162float(h));
}

// ---------------- bf16x3-split GEMM (NT): C = alpha * A @ B^T ----------------
// A,B stored K-major as (hi,lo) bf16 pairs. acc = AhBh + AhBl + AlBh (fp32).
// modes: 0 fp32*alpha store; 1 split+bias store; 2 transposed split+bias ([B][D][S]);
//        4 bias+relu+resid fp32.
// lenmode: 1 skip n-tiles >= len (scores); 2 truncate K at len (PV).
#define BKE 32
#define TILE_B 8192          // 128 rows * 32 bf16 * 2B
#define STAGE_B (4*TILE_B)   // Ah, Al, Bh, Bl
#define NSTG 3
#define GEMM_SMEM (NSTG*STAGE_B)   // 98304

#define SW(row, c) (((c) ^ ((row) >> 1)) & 3)

__global__ void __launch_bounds__(256, 1) gemm_bf3(
    const __nv_bfloat16* __restrict__ Ah, const __nv_bfloat16* __restrict__ Al,
    const __nv_bfloat16* __restrict__ Bh, const __nv_bfloat16* __restrict__ Bl,
    int K, long sA, long sB,
    int mode, float alpha, const float* __restrict__ bias,
    const float* __restrict__ resid,
    float* __restrict__ C, long strideC, int ldc,
    __nv_bfloat16* __restrict__ Coh, __nv_bfloat16* __restrict__ Col,
    const int* __restrict__ lens, int lenmode)
{
    extern __shared__ char smem[];
    const int t = threadIdx.x, wid = t >> 5, l = t & 31;
    const int m0 = blockIdx.y * 128, n0 = blockIdx.x * 128, bz = blockIdx.z;

    int nc = K / BKE;
    if (lenmode == 1) { if (n0 >= __ldg(lens + bz)) return; }
    if (lenmode == 2) { int len = __ldg(lens + bz); int kk = (len + BKE - 1) & ~(BKE - 1); if (kk < K) nc = kk / BKE; }

    const __nv_bfloat16* pAh = Ah + (long)bz * sA;
    const __nv_bfloat16* pAl = Al + (long)bz * sA;
    const __nv_bfloat16* pBh = Bh + (long)bz * sB;
    const __nv_bfloat16* pBl = Bl + (long)bz * sB;

    const uint32_t sb = smem_u32(smem);
    const int wm = (wid & 3) * 32, wn = (wid >> 2) * 64;

    float acc[2][8][4];
#pragma unroll
    for (int i = 0; i < 2; i++)
#pragma unroll
        for (int j = 0; j < 8; j++)
#pragma unroll
            for (int e = 0; e < 4; e++) acc[i][j][e] = 0.f;

    auto issue = [&](int c, int s) {
        const long k0 = (long)c * BKE;
        const uint32_t stg = sb + (uint32_t)s * STAGE_B;
#pragma unroll
        for (int j = 0; j < 2; j++) {
            int idx = t + j * 256;
            int row = idx >> 2, ch = idx & 3;
            uint32_t off = (uint32_t)row * 64 + (SW(row, ch) << 4);
            long ga = (long)(m0 + row) * K + k0 + ch * 8;
            long gb = (long)(n0 + row) * K + k0 + ch * 8;
            CP_ASYNC16(stg + off,              (const void*)(pAh + ga));
            CP_ASYNC16(stg + TILE_B + off,     (const void*)(pAl + ga));
            CP_ASYNC16(stg + 2 * TILE_B + off, (const void*)(pBh + gb));
            CP_ASYNC16(stg + 3 * TILE_B + off, (const void*)(pBl + gb));
        }
    };

    issue(0, 0); CP_COMMIT();
    if (nc > 1) issue(1, 1);
    CP_COMMIT();

    for (int i = 0; i < nc; i++) {
        CP_WAIT1();
        __syncthreads();
        const uint32_t stg = sb + (uint32_t)(i % NSTG) * STAGE_B;
#pragma unroll
        for (int sub = 0; sub < 2; sub++) {
            uint32_t ahf[2][4], alf[2][4], bhf[4][4], blf[4][4];
            const int ch = sub * 2 + (l >> 4);
#pragma unroll
            for (int mt = 0; mt < 2; mt++) {
                int r = wm + mt * 16 + (l & 15);
                uint32_t off = (uint32_t)r * 64 + (SW(r, ch) << 4);
                ldmx4(ahf[mt], stg + off);
                ldmx4(alf[mt], stg + TILE_B + off);
            }
#pragma unroll
            for (int nt = 0; nt < 4; nt++) {
                int r = wn + nt * 16 + (l & 15);
                uint32_t off = (uint32_t)r * 64 + (SW(r, ch) << 4);
                ldmx4(bhf[nt], stg + 2 * TILE_B + off);
                ldmx4(blf[nt], stg + 3 * TILE_B + off);
            }
#pragma unroll
            for (int mt = 0; mt < 2; mt++)
#pragma unroll
                for (int nt = 0; nt < 4; nt++) {
                    mma16816(acc[mt][2 * nt],     ahf[mt], bhf[nt][0], bhf[nt][2]);
                    mma16816(acc[mt][2 * nt + 1], ahf[mt], bhf[nt][1], bhf[nt][3]);
                    mma16816(acc[mt][2 * nt],     ahf[mt], blf[nt][0], blf[nt][2]);
                    mma16816(acc[mt][2 * nt + 1], ahf[mt], blf[nt][1], blf[nt][3]);
                    mma16816(acc[mt][2 * nt],     alf[mt], bhf[nt][0], bhf[nt][2]);
                    mma16816(acc[mt][2 * nt + 1], alf[mt], bhf[nt][1], bhf[nt][3]);
                }
        }
        if (i + 2 < nc) issue(i + 2, (i + 2) % NSTG);
        CP_COMMIT();
    }

    // ---------------- epilogue ----------------
#pragma unroll
    for (int mt = 0; mt < 2; mt++) {
#pragma unroll
        for (int nt = 0; nt < 8; nt++) {
            const int col = n0 + wn + nt * 8 + (l & 3) * 2;
#pragma unroll
            for (int h = 0; h < 2; h++) {
                const int row = m0 + wm + mt * 16 + (l >> 2) + h * 8;
                float v0 = acc[mt][nt][h * 2], v1 = acc[mt][nt][h * 2 + 1];
                if (mode == 0) {
                    float2 o = make_float2(v0 * alpha, v1 * alpha);
                    *(float2*)(C + (long)bz * strideC + (long)row * ldc + col) = o;
                } else if (mode == 1) {
                    float x0 = v0 + __ldg(bias + col);
                    float x1 = v1 + __ldg(bias + col + 1);
                    __nv_bfloat16 h0, l0, h1, l1;
                    splitf(x0, h0, l0); splitf(x1, h1, l1);
                    __nv_bfloat162 hv; hv.x = h0; hv.y = h1;
                    __nv_bfloat162 lv; lv.x = l0; lv.y = l1;
                    *(__nv_bfloat162*)(Coh + (long)row * ldc + col) = hv;
                    *(__nv_bfloat162*)(Col + (long)row * ldc + col) = lv;
                } else if (mode == 2) {
                    float x0 = v0 + __ldg(bias + col);
                    float x1 = v1 + __ldg(bias + col + 1);
                    __nv_bfloat16 h0, l0, h1, l1;
                    splitf(x0, h0, l0); splitf(x1, h1, l1);
                    int b = row >> 11, s = row & (NS - 1);
                    long a0 = ((long)b * ND + col) * (long)NS + s;
                    Coh[a0] = h0;      Col[a0] = l0;
                    Coh[a0 + NS] = h1; Col[a0 + NS] = l1;
                } else {               // mode 4: bias + relu + resid
                    long a = (long)row * ldc + col;
                    float2 r2 = *(const float2*)(resid + a);
                    float2 o;
                    o.x = fmaxf(v0 + __ldg(bias + col), 0.f) + r2.x;
                    o.y = fmaxf(v1 + __ldg(bias + col + 1), 0.f) + r2.y;
                    *(float2*)(C + a) = o;
                }
            }
        }
    }
}

// ---------------- elementwise: split fp32 -> (bf16 hi, bf16 lo) ----------------
__global__ void split_bf(const float* __restrict__ x, __nv_bfloat16* __restrict__ h,
                         __nv_bfloat16* __restrict__ l, int n4)
{
    int i = blockIdx.x * 256 + threadIdx.x;
    if (i >= n4) return;
    float4 v = ((const float4*)x)[i];
    __nv_bfloat16 h0, l0, h1, l1, h2, l2, h3, l3;
    splitf(v.x, h0, l0); splitf(v.y, h1, l1);
    splitf(v.z, h2, l2); splitf(v.w, h3, l3);
    __nv_bfloat162 ha, hb, la, lb;
    ha.x = h0; ha.y = h1; hb.x = h2; hb.y = h3;
    la.x = l0; la.y = l1; lb.x = l2; lb.y = l3;
    ((__nv_bfloat162*)h)[2 * i] = ha; ((__nv_bfloat162*)h)[2 * i + 1] = hb;
    ((__nv_bfloat162*)l)[2 * i] = la; ((__nv_bfloat162*)l)[2 * i + 1] = lb;
}

// ---------------- masked row softmax -> split bf16 P ----------------
__global__ void softmax_rows(const float* __restrict__ sc, __nv_bfloat16* __restrict__ sch,
                             __nv_bfloat16* __restrict__ scl, const int* __restrict__ lens)
{
    __shared__ float red[256];
    const int t = threadIdx.x;
    const int q = blockIdx.x, b = blockIdx.y;
    const long base = ((long)b * NS + q) * NS;
    const float* row = sc + base;
    const int len = __ldg(lens + b);

    float m = -3.4e38f;
    for (int j = t; j < len; j += 256) m = fmaxf(m, row[j]);
    red[t] = m; __syncthreads();
    for (int s = 128; s > 0; s >>= 1) {
        if (t < s) red[t] = fmaxf(red[t], red[t + s]);
        __syncthreads();
    }
    m = red[0]; __syncthreads();

    float sum = 0.f;
    for (int j = t; j < len; j += 256) sum += __expf(row[j] - m);
    red[t] = sum; __syncthreads();
    for (int s = 128; s > 0; s >>= 1) {
        if (t < s) red[t] += red[t + s];
        __syncthreads();
    }
    const float inv = 1.0f / red[0];

    for (int j = t; j < NS; j += 256) {
        float p = (j < len) ? __expf(row[j] - m) * inv : 0.f;
        __nv_bfloat16 h, lo;
        splitf(p, h, lo);
        sch[base + j] = h;
        scl[base + j] = lo;
    }
}

// ---------------- (optional resid) + LayerNorm (+optional bf16 split out) ----------------
__global__ void add_ln(const float* __restrict__ x, const float* __restrict__ res,
                       const float* __restrict__ g, const float* __restrict__ bt,
                       float* __restrict__ out, __nv_bfloat16* __restrict__ outh,
                       __nv_bfloat16* __restrict__ outl)
{
    __shared__ float r1[256], r2[256];
    const int t = threadIdx.x;
    const long row = blockIdx.x;

    float4 v = ((const float4*)(x + row * ND))[t];
    if (res) {
        float4 w = ((const float4*)(res + row * ND))[t];
        v.x += w.x; v.y += w.y; v.z += w.z; v.w += w.w;
    }
    float s  = v.x + v.y + v.z + v.w;
    float ss = v.x * v.x + v.y * v.y + v.z * v.z + v.w * v.w;
    r1[t] = s; r2[t] = ss; __syncthreads();
    for (int k = 128; k > 0; k >>= 1) {
        if (t < k) { r1[t] += r1[t + k]; r2[t] += r2[t + k]; }
        __syncthreads();
    }
    const float mean = r1[0] * (1.0f / ND);
    const float var  = r2[0] * (1.0f / ND) - mean * mean;
    const float inv  = rsqrtf(var + 1e-5f);

    float4 gg = ((const float4*)g)[t];
    float4 bb = ((const float4*)bt)[t];
    float4 o;
    o.x = (v.x - mean) * inv * gg.x + bb.x;
    o.y = (v.y - mean) * inv * gg.y + bb.y;
    o.z = (v.z - mean) * inv * gg.z + bb.z;
    o.w = (v.w - mean) * inv * gg.w + bb.w;
    if (out) ((float4*)(out + row * ND))[t] = o;
    if (outh) {
        __nv_bfloat16 h0, l0, h1, l1, h2, l2, h3, l3;
        splitf(o.x, h0, l0); splitf(o.y, h1, l1);
        splitf(o.z, h2, l2); splitf(o.w, h3, l3);
        __nv_bfloat162 ha, hb, la, lb;
        ha.x = h0; ha.y = h1; hb.x = h2; hb.y = h3;
        la.x = l0; la.y = l1; lb.x = l2; lb.y = l3;
        long p = row * (ND / 2) + 2 * t;
        ((__nv_bfloat162*)outh)[p] = ha; ((__nv_bfloat162*)outh)[p + 1] = hb;
        ((__nv_bfloat162*)outl)[p] = la; ((__nv_bfloat162*)outl)[p + 1] = lb;
    }
}

// ---------------- launch ----------------
extern "C" void kernel_launch(void* const* d_in, const int* in_sizes, int n_in,
                              void* d_out, int out_size)
{
    const float* seq  = (const float*)d_in[0];
    const int*   lens = (const int*)  d_in[1];
    const float* Wq = (const float*)d_in[2];
    const float* bq = (const float*)d_in[3];
    const float* Wk = (const float*)d_in[4];
    const float* bk = (const float*)d_in[5];
    const float* Wv = (const float*)d_in[6];
    const float* bv = (const float*)d_in[7];
    const float* Wo = (const float*)d_in[8];
    const float* bo = (const float*)d_in[9];
    const float* g1 = (const float*)d_in[10];
    const float* b1 = (const float*)d_in[11];
    const float* g2 = (const float*)d_in[12];
    const float* b2 = (const float*)d_in[13];
    float* out = (float*)d_out;

    static bool init_done = false;
    if (!init_done) {
        cudaFuncSetAttribute(gemm_bf3, cudaFuncAttributeMaxDynamicSharedMemorySize, GEMM_SMEM);
        init_done = true;
    }

    struct Ptrs {
        __nv_bfloat16 *seqh, *seql, *wqh, *wql, *wkh, *wkl, *wvh, *wvl, *woh, *wol;
        __nv_bfloat16 *qh, *ql, *kh, *kl, *vth, *vtl, *sch, *scl, *posth, *postl;
        float *sc, *attn, *post, *ffn;
    };
    static Ptrs P;
    static bool sym_done = false;
    if (!sym_done) {
        cudaGetSymbolAddress((void**)&P.seqh, g_seqh);   cudaGetSymbolAddress((void**)&P.seql, g_seql);
        cudaGetSymbolAddress((void**)&P.wqh,  g_wqh);    cudaGetSymbolAddress((void**)&P.wql,  g_wql);
        cudaGetSymbolAddress((void**)&P.wkh,  g_wkh);    cudaGetSymbolAddress((void**)&P.wkl,  g_wkl);
        cudaGetSymbolAddress((void**)&P.wvh,  g_wvh);    cudaGetSymbolAddress((void**)&P.wvl,  g_wvl);
        cudaGetSymbolAddress((void**)&P.woh,  g_woh);    cudaGetSymbolAddress((void**)&P.wol,  g_wol);
        cudaGetSymbolAddress((void**)&P.qh,   g_qh);     cudaGetSymbolAddress((void**)&P.ql,   g_ql);
        cudaGetSymbolAddress((void**)&P.kh,   g_kh);     cudaGetSymbolAddress((void**)&P.kl,   g_kl);
        cudaGetSymbolAddress((void**)&P.vth,  g_vth);    cudaGetSymbolAddress((void**)&P.vtl,  g_vtl);
        cudaGetSymbolAddress((void**)&P.sch,  g_sch);    cudaGetSymbolAddress((void**)&P.scl,  g_scl);
        cudaGetSymbolAddress((void**)&P.posth,g_posth);  cudaGetSymbolAddress((void**)&P.postl,g_postl);
        cudaGetSymbolAddress((void**)&P.sc,   g_sc);     cudaGetSymbolAddress((void**)&P.attn, g_attn);
        cudaGetSymbolAddress((void**)&P.post, g_post);   cudaGetSymbolAddress((void**)&P.ffn,  g_ffn);
        sym_done = true;
    }

    const long SD  = (long)NS * ND;
    const long SS2 = (long)NS * NS;

    // ---- split inputs to bf16 hi/lo ----
    split_bf<<<(NB * NS * ND) / 1024, 256>>>(seq, P.seqh, P.seql, NB * NS * ND / 4);
    split_bf<<<(ND * ND) / 1024, 256>>>(Wq, P.wqh, P.wql, ND * ND / 4);
    split_bf<<<(ND * ND) / 1024, 256>>>(Wk, P.wkh, P.wkl, ND * ND / 4);
    split_bf<<<(ND * ND) / 1024, 256>>>(Wv, P.wvh, P.wvl, ND * ND / 4);
    split_bf<<<(ND * ND) / 1024, 256>>>(Wo, P.woh, P.wol, ND * ND / 4);

    const dim3 blk(256);
    const dim3 gproj(ND / 128, (NB * NS) / 128, 1);

    // Q, K projections (split-store); V projection (transposed split-store)
    gemm_bf3<<<gproj, blk, GEMM_SMEM>>>(P.seqh, P.seql, P.wqh, P.wql, ND, 0, 0,
        1, 1.f, bq, nullptr, nullptr, 0, ND, P.qh, P.ql, nullptr, 0);
    gemm_bf3<<<gproj, blk, GEMM_SMEM>>>(P.seqh, P.seql, P.wkh, P.wkl, ND, 0, 0,
        1, 1.f, bk, nullptr, nullptr, 0, ND, P.kh, P.kl, nullptr, 0);
    gemm_bf3<<<gproj, blk, GEMM_SMEM>>>(P.seqh, P.seql, P.wvh, P.wvl, ND, 0, 0,
        2, 1.f, bv, nullptr, nullptr, 0, ND, P.vth, P.vtl, nullptr, 0);

    // scores = Q K^T / 32 (masked n-tiles skipped)
    gemm_bf3<<<dim3(NS / 128, NS / 128, NB), blk, GEMM_SMEM>>>(
        P.qh, P.ql, P.kh, P.kl, ND, SD, SD,
        0, 1.0f / 32.0f, nullptr, nullptr, P.sc, SS2, NS, nullptr, nullptr, lens, 1);

    softmax_rows<<<dim3(NS, NB), blk>>>(P.sc, P.sch, P.scl, lens);

    // attn = P @ V (B-operand = V^T, K truncated at len)
    gemm_bf3<<<dim3(ND / 128, NS / 128, NB), blk, GEMM_SMEM>>>(
        P.sch, P.scl, P.vth, P.vtl, NS, SS2, SD,
        0, 1.f, nullptr, nullptr, P.attn, SD, ND, nullptr, nullptr, lens, 2);

    // post = LN(seq + attn), also split for FFN A-operand
    add_ln<<<NB * NS, blk>>>(P.attn, seq, g1, b1, P.post, P.posth, P.postl);

    // ffn = relu(post @ Wo^T + bo) + post
    gemm_bf3<<<gproj, blk, GEMM_SMEM>>>(P.posth, P.postl, P.woh, P.wol, ND, 0, 0,
        4, 1.f, bo, P.post, P.ffn, 0, ND, nullptr, nullptr, nullptr, 0);

    // out = LN(ffn)
    add_ln<<<NB * NS, blk>>>(P.ffn, nullptr, g2, b2, out, nullptr, nullptr);
}

// round 7
// speedup vs baseline: 2.2437x; 1.0523x over previous
#include <cuda_runtime.h>
#include <cuda_bf16.h>
#include <cstdint>

#define NB 8
#define NS 2048
#define ND 1024

// ---------------- scratch (device globals; no allocs allowed) ----------------
__device__ __nv_bfloat16 g_seqh[NB*NS*ND], g_seql[NB*NS*ND];
__device__ __nv_bfloat16 g_wqh[ND*ND], g_wql[ND*ND];
__device__ __nv_bfloat16 g_wkh[ND*ND], g_wkl[ND*ND];
__device__ __nv_bfloat16 g_wvh[ND*ND], g_wvl[ND*ND];
__device__ __nv_bfloat16 g_woh[ND*ND], g_wol[ND*ND];
__device__ __nv_bfloat16 g_qh[NB*NS*ND], g_ql[NB*NS*ND];
__device__ __nv_bfloat16 g_kh[NB*NS*ND], g_kl[NB*NS*ND];
__device__ __nv_bfloat16 g_vth[NB*NS*ND], g_vtl[NB*NS*ND];   // V^T: [B][D][S]
__device__ __nv_bfloat16 g_sch[NB*NS*NS], g_scl[NB*NS*NS];   // split softmax P
__device__ __nv_bfloat16 g_posth[NB*NS*ND], g_postl[NB*NS*ND];
__device__ float g_sc[NB*NS*NS];
__device__ float g_attn[NB*NS*ND];
__device__ float g_post[NB*NS*ND];
__device__ float g_ffn[NB*NS*ND];

// ---------------- PTX helpers (all compute_100-legal: sm_80-era) ----------------
__device__ __forceinline__ uint32_t smem_u32(const void* p) {
    uint32_t a;
    asm("{ .reg .u64 t; cvta.to.shared.u64 t, %1; cvt.u32.u64 %0, t; }" : "=r"(a) : "l"(p));
    return a;
}

#define CP_ASYNC16(s, g) \
    asm volatile("cp.async.cg.shared.global [%0], [%1], 16;" :: "r"(s), "l"(g) : "memory")
#define CP_COMMIT() asm volatile("cp.async.commit_group;" ::: "memory")
#define CP_WAIT1()  asm volatile("cp.async.wait_group 1;" ::: "memory")

__device__ __forceinline__ void ldmx4(uint32_t r[4], uint32_t a) {
    asm volatile("ldmatrix.sync.aligned.m8n8.x4.shared.b16 {%0,%1,%2,%3}, [%4];"
        : "=r"(r[0]), "=r"(r[1]), "=r"(r[2]), "=r"(r[3]) : "r"(a));
}

__device__ __forceinline__ void mma16816(float c[4], const uint32_t a[4],
                                         uint32_t b0, uint32_t b1) {
    asm volatile("mma.sync.aligned.m16n8k16.row.col.f32.bf16.bf16.f32 "
        "{%0,%1,%2,%3}, {%4,%5,%6,%7}, {%8,%9}, {%0,%1,%2,%3};"
        : "+f"(c[0]), "+f"(c[1]), "+f"(c[2]), "+f"(c[3])
        : "r"(a[0]), "r"(a[1]), "r"(a[2]), "r"(a[3]), "r"(b0), "r"(b1));
}

__device__ __forceinline__ void splitf(float x, __nv_bfloat16& h, __nv_bfloat16& l) {
    h = __float2bfloat16(x);
    l = __float2bfloat16(x - __bfloat162float(h));
}

// ---------------- bf16x3-split GEMM (NT): C = alpha * A @ B^T ----------------
// A,B stored K-major as (hi,lo) bf16 pairs. acc = AhBh + AhBl + AlBh (fp32).
// modes: 0 fp32*alpha store; 1 split+bias store; 2 transposed split+bias ([B][D][S]);
//        4 bias+relu+resid fp32.
// lenmode: 1 skip n-tiles >= len (scores); 2 truncate K at len (PV);
//          3 skip m-tiles whose in-batch row >= len (K/V projections).
#define BKE 32
#define TILE_B 8192          // 128 rows * 32 bf16 * 2B
#define STAGE_B (4*TILE_B)   // Ah, Al, Bh, Bl
#define NSTG 3
#define GEMM_SMEM (NSTG*STAGE_B)   // 98304

#define SW(row, c) (((c) ^ ((row) >> 1)) & 3)

__global__ void __launch_bounds__(256, 1) gemm_bf3(
    const __nv_bfloat16* __restrict__ Ah, const __nv_bfloat16* __restrict__ Al,
    const __nv_bfloat16* __restrict__ Bh, const __nv_bfloat16* __restrict__ Bl,
    int K, long sA, long sB,
    int mode, float alpha, const float* __restrict__ bias,
    const float* __restrict__ resid,
    float* __restrict__ C, long strideC, int ldc,
    __nv_bfloat16* __restrict__ Coh, __nv_bfloat16* __restrict__ Col,
    const int* __restrict__ lens, int lenmode)
{
    extern __shared__ char smem[];
    const int t = threadIdx.x, wid = t >> 5, l = t & 31;
    const int m0 = blockIdx.y * 128, n0 = blockIdx.x * 128, bz = blockIdx.z;

    int nc = K / BKE;
    if (lenmode == 1) { if (n0 >= __ldg(lens + bz)) return; }
    if (lenmode == 2) { int len = __ldg(lens + bz); int kk = (len + BKE - 1) & ~(BKE - 1); if (kk < K) nc = kk / BKE; }
    if (lenmode == 3) { if ((m0 & (NS - 1)) >= __ldg(lens + (m0 >> 11))) return; }

    const __nv_bfloat16* pAh = Ah + (long)bz * sA;
    const __nv_bfloat16* pAl = Al + (long)bz * sA;
    const __nv_bfloat16* pBh = Bh + (long)bz * sB;
    const __nv_bfloat16* pBl = Bl + (long)bz * sB;

    const uint32_t sb = smem_u32(smem);
    const int wm = (wid & 3) * 32, wn = (wid >> 2) * 64;

    float acc[2][8][4];
#pragma unroll
    for (int i = 0; i < 2; i++)
#pragma unroll
        for (int j = 0; j < 8; j++)
#pragma unroll
            for (int e = 0; e < 4; e++) acc[i][j][e] = 0.f;

    auto issue = [&](int c, int s) {
        const long k0 = (long)c * BKE;
        const uint32_t stg = sb + (uint32_t)s * STAGE_B;
#pragma unroll
        for (int j = 0; j < 2; j++) {
            int idx = t + j * 256;
            int row = idx >> 2, ch = idx & 3;
            uint32_t off = (uint32_t)row * 64 + (SW(row, ch) << 4);
            long ga = (long)(m0 + row) * K + k0 + ch * 8;
            long gb = (long)(n0 + row) * K + k0 + ch * 8;
            CP_ASYNC16(stg + off,              (const void*)(pAh + ga));
            CP_ASYNC16(stg + TILE_B + off,     (const void*)(pAl + ga));
            CP_ASYNC16(stg + 2 * TILE_B + off, (const void*)(pBh + gb));
            CP_ASYNC16(stg + 3 * TILE_B + off, (const void*)(pBl + gb));
        }
    };

    issue(0, 0); CP_COMMIT();
    if (nc > 1) issue(1, 1);
    CP_COMMIT();

    for (int i = 0; i < nc; i++) {
        CP_WAIT1();
        __syncthreads();
        const uint32_t stg = sb + (uint32_t)(i % NSTG) * STAGE_B;
#pragma unroll
        for (int sub = 0; sub < 2; sub++) {
            uint32_t ahf[2][4], alf[2][4], bhf[4][4], blf[4][4];
            const int ch = sub * 2 + (l >> 4);
#pragma unroll
            for (int mt = 0; mt < 2; mt++) {
                int r = wm + mt * 16 + (l & 15);
                uint32_t off = (uint32_t)r * 64 + (SW(r, ch) << 4);
                ldmx4(ahf[mt], stg + off);
                ldmx4(alf[mt], stg + TILE_B + off);
            }
#pragma unroll
            for (int nt = 0; nt < 4; nt++) {
                int r = wn + nt * 16 + (l & 15);
                uint32_t off = (uint32_t)r * 64 + (SW(r, ch) << 4);
                ldmx4(bhf[nt], stg + 2 * TILE_B + off);
                ldmx4(blf[nt], stg + 3 * TILE_B + off);
            }
            // term-outer ordering: 16 independent MMAs per term (acc reuse
            // distance 16 instead of 1 -> hides HMMA latency)
#pragma unroll
            for (int mt = 0; mt < 2; mt++)
#pragma unroll
                for (int nt = 0; nt < 4; nt++) {
                    mma16816(acc[mt][2 * nt],     ahf[mt], bhf[nt][0], bhf[nt][2]);
                    mma16816(acc[mt][2 * nt + 1], ahf[mt], bhf[nt][1], bhf[nt][3]);
                }
#pragma unroll
            for (int mt = 0; mt < 2; mt++)
#pragma unroll
                for (int nt = 0; nt < 4; nt++) {
                    mma16816(acc[mt][2 * nt],     ahf[mt], blf[nt][0], blf[nt][2]);
                    mma16816(acc[mt][2 * nt + 1], ahf[mt], blf[nt][1], blf[nt][3]);
                }
#pragma unroll
            for (int mt = 0; mt < 2; mt++)
#pragma unroll
                for (int nt = 0; nt < 4; nt++) {
                    mma16816(acc[mt][2 * nt],     alf[mt], bhf[nt][0], bhf[nt][2]);
                    mma16816(acc[mt][2 * nt + 1], alf[mt], bhf[nt][1], bhf[nt][3]);
                }
        }
        if (i + 2 < nc) issue(i + 2, (i + 2) % NSTG);
        CP_COMMIT();
    }

    // ---------------- epilogue ----------------
#pragma unroll
    for (int mt = 0; mt < 2; mt++) {
#pragma unroll
        for (int nt = 0; nt < 8; nt++) {
            const int col = n0 + wn + nt * 8 + (l & 3) * 2;
#pragma unroll
            for (int h = 0; h < 2; h++) {
                const int row = m0 + wm + mt * 16 + (l >> 2) + h * 8;
                float v0 = acc[mt][nt][h * 2], v1 = acc[mt][nt][h * 2 + 1];
                if (mode == 0) {
                    float2 o = make_float2(v0 * alpha, v1 * alpha);
                    *(float2*)(C + (long)bz * strideC + (long)row * ldc + col) = o;
                } else if (mode == 1) {
                    float x0 = v0 + __ldg(bias + col);
                    float x1 = v1 + __ldg(bias + col + 1);
                    __nv_bfloat16 h0, l0, h1, l1;
                    splitf(x0, h0, l0); splitf(x1, h1, l1);
                    __nv_bfloat162 hv; hv.x = h0; hv.y = h1;
                    __nv_bfloat162 lv; lv.x = l0; lv.y = l1;
                    *(__nv_bfloat162*)(Coh + (long)row * ldc + col) = hv;
                    *(__nv_bfloat162*)(Col + (long)row * ldc + col) = lv;
                } else if (mode == 2) {
                    float x0 = v0 + __ldg(bias + col);
                    float x1 = v1 + __ldg(bias + col + 1);
                    __nv_bfloat16 h0, l0, h1, l1;
                    splitf(x0, h0, l0); splitf(x1, h1, l1);
                    int b = row >> 11, s = row & (NS - 1);
                    long a0 = ((long)b * ND + col) * (long)NS + s;
                    Coh[a0] = h0;      Col[a0] = l0;
                    Coh[a0 + NS] = h1; Col[a0 + NS] = l1;
                } else {               // mode 4: bias + relu + resid
                    long a = (long)row * ldc + col;
                    float2 r2 = *(const float2*)(resid + a);
                    float2 o;
                    o.x = fmaxf(v0 + __ldg(bias + col), 0.f) + r2.x;
                    o.y = fmaxf(v1 + __ldg(bias + col + 1), 0.f) + r2.y;
                    *(float2*)(C + a) = o;
                }
            }
        }
    }
}

// ---------------- elementwise: split fp32 -> (bf16 hi, bf16 lo) ----------------
__global__ void split_bf(const float* __restrict__ x, __nv_bfloat16* __restrict__ h,
                         __nv_bfloat16* __restrict__ l, int n4)
{
    int i = blockIdx.x * 256 + threadIdx.x;
    if (i >= n4) return;
    float4 v = ((const float4*)x)[i];
    __nv_bfloat16 h0, l0, h1, l1, h2, l2, h3, l3;
    splitf(v.x, h0, l0); splitf(v.y, h1, l1);
    splitf(v.z, h2, l2); splitf(v.w, h3, l3);
    __nv_bfloat162 ha, hb, la, lb;
    ha.x = h0; ha.y = h1; hb.x = h2; hb.y = h3;
    la.x = l0; la.y = l1; lb.x = l2; lb.y = l3;
    ((__nv_bfloat162*)h)[2 * i] = ha; ((__nv_bfloat162*)h)[2 * i + 1] = hb;
    ((__nv_bfloat162*)l)[2 * i] = la; ((__nv_bfloat162*)l)[2 * i + 1] = lb;
}

// ---------------- masked row softmax -> split bf16 P ----------------
__global__ void softmax_rows(const float* __restrict__ sc, __nv_bfloat16* __restrict__ sch,
                             __nv_bfloat16* __restrict__ scl, const int* __restrict__ lens)
{
    __shared__ float red[256];
    const int t = threadIdx.x;
    const int q = blockIdx.x, b = blockIdx.y;
    const long base = ((long)b * NS + q) * NS;
    const float* row = sc + base;
    const int len = __ldg(lens + b);
    const int wlim = (len + BKE - 1) & ~(BKE - 1);   // PV never reads past this

    float m = -3.4e38f;
    for (int j = t; j < len; j += 256) m = fmaxf(m, row[j]);
    red[t] = m; __syncthreads();
    for (int s = 128; s > 0; s >>= 1) {
        if (t < s) red[t] = fmaxf(red[t], red[t + s]);
        __syncthreads();
    }
    m = red[0]; __syncthreads();

    float sum = 0.f;
    for (int j = t; j < len; j += 256) sum += __expf(row[j] - m);
    red[t] = sum; __syncthreads();
    for (int s = 128; s > 0; s >>= 1) {
        if (t < s) red[t] += red[t + s];
        __syncthreads();
    }
    const float inv = 1.0f / red[0];

    for (int j = t; j < wlim; j += 256) {
        float p = (j < len) ? __expf(row[j] - m) * inv : 0.f;
        __nv_bfloat16 h, lo;
        splitf(p, h, lo);
        sch[base + j] = h;
        scl[base + j] = lo;
    }
}

// ---------------- (optional resid) + LayerNorm (+optional bf16 split out) ----------------
__global__ void add_ln(const float* __restrict__ x, const float* __restrict__ res,
                       const float* __restrict__ g, const float* __restrict__ bt,
                       float* __restrict__ out, __nv_bfloat16* __restrict__ outh,
                       __nv_bfloat16* __restrict__ outl)
{
    __shared__ float r1[256], r2[256];
    const int t = threadIdx.x;
    const long row = blockIdx.x;

    float4 v = ((const float4*)(x + row * ND))[t];
    if (res) {
        float4 w = ((const float4*)(res + row * ND))[t];
        v.x += w.x; v.y += w.y; v.z += w.z; v.w += w.w;
    }
    float s  = v.x + v.y + v.z + v.w;
    float ss = v.x * v.x + v.y * v.y + v.z * v.z + v.w * v.w;
    r1[t] = s; r2[t] = ss; __syncthreads();
    for (int k = 128; k > 0; k >>= 1) {
        if (t < k) { r1[t] += r1[t + k]; r2[t] += r2[t + k]; }
        __syncthreads();
    }
    const float mean = r1[0] * (1.0f / ND);
    const float var  = r2[0] * (1.0f / ND) - mean * mean;
    const float inv  = rsqrtf(var + 1e-5f);

    float4 gg = ((const float4*)g)[t];
    float4 bb = ((const float4*)bt)[t];
    float4 o;
    o.x = (v.x - mean) * inv * gg.x + bb.x;
    o.y = (v.y - mean) * inv * gg.y + bb.y;
    o.z = (v.z - mean) * inv * gg.z + bb.z;
    o.w = (v.w - mean) * inv * gg.w + bb.w;
    if (out) ((float4*)(out + row * ND))[t] = o;
    if (outh) {
        __nv_bfloat16 h0, l0, h1, l1, h2, l2, h3, l3;
        splitf(o.x, h0, l0); splitf(o.y, h1, l1);
        splitf(o.z, h2, l2); splitf(o.w, h3, l3);
        __nv_bfloat162 ha, hb, la, lb;
        ha.x = h0; ha.y = h1; hb.x = h2; hb.y = h3;
        la.x = l0; la.y = l1; lb.x = l2; lb.y = l3;
        long p = row * (ND / 2) + 2 * t;
        ((__nv_bfloat162*)outh)[p] = ha; ((__nv_bfloat162*)outh)[p + 1] = hb;
        ((__nv_bfloat162*)outl)[p] = la; ((__nv_bfloat162*)outl)[p + 1] = lb;
    }
}

// ---------------- launch ----------------
extern "C" void kernel_launch(void* const* d_in, const int* in_sizes, int n_in,
                              void* d_out, int out_size)
{
    const float* seq  = (const float*)d_in[0];
    const int*   lens = (const int*)  d_in[1];
    const float* Wq = (const float*)d_in[2];
    const float* bq = (const float*)d_in[3];
    const float* Wk = (const float*)d_in[4];
    const float* bk = (const float*)d_in[5];
    const float* Wv = (const float*)d_in[6];
    const float* bv = (const float*)d_in[7];
    const float* Wo = (const float*)d_in[8];
    const float* bo = (const float*)d_in[9];
    const float* g1 = (const float*)d_in[10];
    const float* b1 = (const float*)d_in[11];
    const float* g2 = (const float*)d_in[12];
    const float* b2 = (const float*)d_in[13];
    float* out = (float*)d_out;

    static bool init_done = false;
    if (!init_done) {
        cudaFuncSetAttribute(gemm_bf3, cudaFuncAttributeMaxDynamicSharedMemorySize, GEMM_SMEM);
        init_done = true;
    }

    struct Ptrs {
        __nv_bfloat16 *seqh, *seql, *wqh, *wql, *wkh, *wkl, *wvh, *wvl, *woh, *wol;
        __nv_bfloat16 *qh, *ql, *kh, *kl, *vth, *vtl, *sch, *scl, *posth, *postl;
        float *sc, *attn, *post, *ffn;
    };
    static Ptrs P;
    static bool sym_done = false;
    if (!sym_done) {
        cudaGetSymbolAddress((void**)&P.seqh, g_seqh);   cudaGetSymbolAddress((void**)&P.seql, g_seql);
        cudaGetSymbolAddress((void**)&P.wqh,  g_wqh);    cudaGetSymbolAddress((void**)&P.wql,  g_wql);
        cudaGetSymbolAddress((void**)&P.wkh,  g_wkh);    cudaGetSymbolAddress((void**)&P.wkl,  g_wkl);
        cudaGetSymbolAddress((void**)&P.wvh,  g_wvh);    cudaGetSymbolAddress((void**)&P.wvl,  g_wvl);
        cudaGetSymbolAddress((void**)&P.woh,  g_woh);    cudaGetSymbolAddress((void**)&P.wol,  g_wol);
        cudaGetSymbolAddress((void**)&P.qh,   g_qh);     cudaGetSymbolAddress((void**)&P.ql,   g_ql);
        cudaGetSymbolAddress((void**)&P.kh,   g_kh);     cudaGetSymbolAddress((void**)&P.kl,   g_kl);
        cudaGetSymbolAddress((void**)&P.vth,  g_vth);    cudaGetSymbolAddress((void**)&P.vtl,  g_vtl);
        cudaGetSymbolAddress((void**)&P.sch,  g_sch);    cudaGetSymbolAddress((void**)&P.scl,  g_scl);
        cudaGetSymbolAddress((void**)&P.posth,g_posth);  cudaGetSymbolAddress((void**)&P.postl,g_postl);
        cudaGetSymbolAddress((void**)&P.sc,   g_sc);     cudaGetSymbolAddress((void**)&P.attn, g_attn);
        cudaGetSymbolAddress((void**)&P.post, g_post);   cudaGetSymbolAddress((void**)&P.ffn,  g_ffn);
        sym_done = true;
    }

    const long SD  = (long)NS * ND;
    const long SS2 = (long)NS * NS;

    // ---- split inputs to bf16 hi/lo ----
    split_bf<<<(NB * NS * ND) / 1024, 256>>>(seq, P.seqh, P.seql, NB * NS * ND / 4);
    split_bf<<<(ND * ND) / 1024, 256>>>(Wq, P.wqh, P.wql, ND * ND / 4);
    split_bf<<<(ND * ND) / 1024, 256>>>(Wk, P.wkh, P.wkl, ND * ND / 4);
    split_bf<<<(ND * ND) / 1024, 256>>>(Wv, P.wvh, P.wvl, ND * ND / 4);
    split_bf<<<(ND * ND) / 1024, 256>>>(Wo, P.woh, P.wol, ND * ND / 4);

    const dim3 blk(256);
    const dim3 gproj(ND / 128, (NB * NS) / 128, 1);

    // Q projection (all rows); K, V projections skip masked-out rows
    gemm_bf3<<<gproj, blk, GEMM_SMEM>>>(P.seqh, P.seql, P.wqh, P.wql, ND, 0, 0,
        1, 1.f, bq, nullptr, nullptr, 0, ND, P.qh, P.ql, nullptr, 0);
    gemm_bf3<<<gproj, blk, GEMM_SMEM>>>(P.seqh, P.seql, P.wkh, P.wkl, ND, 0, 0,
        1, 1.f, bk, nullptr, nullptr, 0, ND, P.kh, P.kl, lens, 3);
    gemm_bf3<<<gproj, blk, GEMM_SMEM>>>(P.seqh, P.seql, P.wvh, P.wvl, ND, 0, 0,
        2, 1.f, bv, nullptr, nullptr, 0, ND, P.vth, P.vtl, lens, 3);

    // scores = Q K^T / 32 (masked n-tiles skipped)
    gemm_bf3<<<dim3(NS / 128, NS / 128, NB), blk, GEMM_SMEM>>>(
        P.qh, P.ql, P.kh, P.kl, ND, SD, SD,
        0, 1.0f / 32.0f, nullptr, nullptr, P.sc, SS2, NS, nullptr, nullptr, lens, 1);

    softmax_rows<<<dim3(NS, NB), blk>>>(P.sc, P.sch, P.scl, lens);

    // attn = P @ V (B-operand = V^T, K truncated at len)
    gemm_bf3<<<dim3(ND / 128, NS / 128, NB), blk, GEMM_SMEM>>>(
        P.sch, P.scl, P.vth, P.vtl, NS, SS2, SD,
        0, 1.f, nullptr, nullptr, P.attn, SD, ND, nullptr, nullptr, lens, 2);

    // post = LN(seq + attn), also split for FFN A-operand
    add_ln<<<NB * NS, blk>>>(P.attn, seq, g1, b1, P.post, P.posth, P.postl);

    // ffn = relu(post @ Wo^T + bo) + post
    gemm_bf3<<<gproj, blk, GEMM_SMEM>>>(P.posth, P.postl, P.woh, P.wol, ND, 0, 0,
        4, 1.f, bo, P.post, P.ffn, 0, ND, nullptr, nullptr, nullptr, 0);

    // out = LN(ffn)
    add_ln<<<NB * NS, blk>>>(P.ffn, nullptr, g2, b2, out, nullptr, nullptr);
}

// round 8
// speedup vs baseline: 2.3039x; 1.0268x over previous
#include <cuda_runtime.h>
#include <cuda_bf16.h>
#include <cstdint>

#define NB 8
#define NS 2048
#define ND 1024

// ---------------- scratch (device globals; no allocs allowed) ----------------
__device__ __nv_bfloat16 g_seqh[NB*NS*ND], g_seql[NB*NS*ND];
__device__ __nv_bfloat16 g_wqh[ND*ND], g_wql[ND*ND];
__device__ __nv_bfloat16 g_wkh[ND*ND], g_wkl[ND*ND];
__device__ __nv_bfloat16 g_wvh[ND*ND], g_wvl[ND*ND];
__device__ __nv_bfloat16 g_woh[ND*ND], g_wol[ND*ND];
__device__ __nv_bfloat16 g_qh[NB*NS*ND], g_ql[NB*NS*ND];
__device__ __nv_bfloat16 g_kh[NB*NS*ND], g_kl[NB*NS*ND];
__device__ __nv_bfloat16 g_vth[NB*NS*ND], g_vtl[NB*NS*ND];   // V^T: [B][D][S]
__device__ __nv_bfloat16 g_sch[NB*NS*NS], g_scl[NB*NS*NS];   // split softmax P
__device__ __nv_bfloat16 g_posth[NB*NS*ND], g_postl[NB*NS*ND];
__device__ float g_sc[NB*NS*NS];
__device__ float g_attn[NB*NS*ND];
__device__ float g_post[NB*NS*ND];
__device__ float g_ffn[NB*NS*ND];

// ---------------- PTX helpers (all compute_100-legal: sm_80-era) ----------------
__device__ __forceinline__ uint32_t smem_u32(const void* p) {
    uint32_t a;
    asm("{ .reg .u64 t; cvta.to.shared.u64 t, %1; cvt.u32.u64 %0, t; }" : "=r"(a) : "l"(p));
    return a;
}

#define CP_ASYNC16(s, g) \
    asm volatile("cp.async.cg.shared.global [%0], [%1], 16;" :: "r"(s), "l"(g) : "memory")
#define CP_COMMIT() asm volatile("cp.async.commit_group;" ::: "memory")
#define CP_WAIT1()  asm volatile("cp.async.wait_group 1;" ::: "memory")

__device__ __forceinline__ void ldmx4(uint32_t r[4], uint32_t a) {
    asm volatile("ldmatrix.sync.aligned.m8n8.x4.shared.b16 {%0,%1,%2,%3}, [%4];"
        : "=r"(r[0]), "=r"(r[1]), "=r"(r[2]), "=r"(r[3]) : "r"(a));
}

__device__ __forceinline__ void mma16816(float c[4], const uint32_t a[4],
                                         uint32_t b0, uint32_t b1) {
    asm volatile("mma.sync.aligned.m16n8k16.row.col.f32.bf16.bf16.f32 "
        "{%0,%1,%2,%3}, {%4,%5,%6,%7}, {%8,%9}, {%0,%1,%2,%3};"
        : "+f"(c[0]), "+f"(c[1]), "+f"(c[2]), "+f"(c[3])
        : "r"(a[0]), "r"(a[1]), "r"(a[2]), "r"(a[3]), "r"(b0), "r"(b1));
}

__device__ __forceinline__ void splitf(float x, __nv_bfloat16& h, __nv_bfloat16& l) {
    h = __float2bfloat16(x);
    l = __float2bfloat16(x - __bfloat162float(h));
}

// ---------------- bf16x3-split GEMM (NT): C = alpha * A @ B^T ----------------
// 512 threads, 4x4 warp grid, 32x32 warp tile, 128x128x32 CTA tile.
// A,B stored K-major as (hi,lo) bf16 pairs. acc = AhBh + AhBl + AlBh (fp32).
// modes: 0 fp32*alpha store; 1 split+bias store; 2 transposed split+bias ([B][D][S]);
//        4 bias+relu+resid fp32.
// lenmode: 1 skip n-tiles >= len (scores); 2 truncate K at len (PV);
//          3 skip m-tiles whose in-batch row >= len (K/V projections).
#define BKE 32
#define TILE_B 8192          // 128 rows * 32 bf16 * 2B
#define STAGE_B (4*TILE_B)   // Ah, Al, Bh, Bl
#define NSTG 3
#define GEMM_SMEM (NSTG*STAGE_B)   // 98304
#define GT 512

#define SW(row, c) (((c) ^ ((row) >> 1)) & 3)

__global__ void __launch_bounds__(GT, 1) gemm_bf3(
    const __nv_bfloat16* __restrict__ Ah, const __nv_bfloat16* __restrict__ Al,
    const __nv_bfloat16* __restrict__ Bh, const __nv_bfloat16* __restrict__ Bl,
    int K, long sA, long sB,
    int mode, float alpha, const float* __restrict__ bias,
    const float* __restrict__ resid,
    float* __restrict__ C, long strideC, int ldc,
    __nv_bfloat16* __restrict__ Coh, __nv_bfloat16* __restrict__ Col,
    const int* __restrict__ lens, int lenmode)
{
    extern __shared__ char smem[];
    const int t = threadIdx.x, wid = t >> 5, l = t & 31;
    const int m0 = blockIdx.y * 128, n0 = blockIdx.x * 128, bz = blockIdx.z;

    int nc = K / BKE;
    if (lenmode == 1) { if (n0 >= __ldg(lens + bz)) return; }
    if (lenmode == 2) { int len = __ldg(lens + bz); int kk = (len + BKE - 1) & ~(BKE - 1); if (kk < K) nc = kk / BKE; }
    if (lenmode == 3) { if ((m0 & (NS - 1)) >= __ldg(lens + (m0 >> 11))) return; }

    const __nv_bfloat16* pAh = Ah + (long)bz * sA;
    const __nv_bfloat16* pAl = Al + (long)bz * sA;
    const __nv_bfloat16* pBh = Bh + (long)bz * sB;
    const __nv_bfloat16* pBl = Bl + (long)bz * sB;

    const uint32_t sb = smem_u32(smem);
    const int wm = (wid & 3) * 32, wn = (wid >> 2) * 32;   // 4x4 warp grid

    float acc[2][4][4];
#pragma unroll
    for (int i = 0; i < 2; i++)
#pragma unroll
        for (int j = 0; j < 4; j++)
#pragma unroll
            for (int e = 0; e < 4; e++) acc[i][j][e] = 0.f;

    auto issue = [&](int c, int s) {
        const long k0 = (long)c * BKE;
        const uint32_t stg = sb + (uint32_t)s * STAGE_B;
        int row = t >> 2, ch = t & 3;                       // 512 threads: one pass
        uint32_t off = (uint32_t)row * 64 + (SW(row, ch) << 4);
        long ga = (long)(m0 + row) * K + k0 + ch * 8;
        long gb = (long)(n0 + row) * K + k0 + ch * 8;
        CP_ASYNC16(stg + off,              (const void*)(pAh + ga));
        CP_ASYNC16(stg + TILE_B + off,     (const void*)(pAl + ga));
        CP_ASYNC16(stg + 2 * TILE_B + off, (const void*)(pBh + gb));
        CP_ASYNC16(stg + 3 * TILE_B + off, (const void*)(pBl + gb));
    };

    issue(0, 0); CP_COMMIT();
    if (nc > 1) issue(1, 1);
    CP_COMMIT();

    for (int i = 0; i < nc; i++) {
        CP_WAIT1();
        __syncthreads();
        const uint32_t stg = sb + (uint32_t)(i % NSTG) * STAGE_B;
#pragma unroll
        for (int sub = 0; sub < 2; sub++) {
            uint32_t ahf[2][4], alf[2][4], bhf[2][4], blf[2][4];
            const int ch = sub * 2 + (l >> 4);
#pragma unroll
            for (int mt = 0; mt < 2; mt++) {
                int r = wm + mt * 16 + (l & 15);
                uint32_t off = (uint32_t)r * 64 + (SW(r, ch) << 4);
                ldmx4(ahf[mt], stg + off);
                ldmx4(alf[mt], stg + TILE_B + off);
            }
#pragma unroll
            for (int bt = 0; bt < 2; bt++) {
                int r = wn + bt * 16 + (l & 15);
                uint32_t off = (uint32_t)r * 64 + (SW(r, ch) << 4);
                ldmx4(bhf[bt], stg + 2 * TILE_B + off);
                ldmx4(blf[bt], stg + 3 * TILE_B + off);
            }
            // term-outer: 8 independent MMAs per term
#pragma unroll
            for (int mt = 0; mt < 2; mt++)
#pragma unroll
                for (int bt = 0; bt < 2; bt++) {
                    mma16816(acc[mt][2 * bt],     ahf[mt], bhf[bt][0], bhf[bt][2]);
                    mma16816(acc[mt][2 * bt + 1], ahf[mt], bhf[bt][1], bhf[bt][3]);
                }
#pragma unroll
            for (int mt = 0; mt < 2; mt++)
#pragma unroll
                for (int bt = 0; bt < 2; bt++) {
                    mma16816(acc[mt][2 * bt],     ahf[mt], blf[bt][0], blf[bt][2]);
                    mma16816(acc[mt][2 * bt + 1], ahf[mt], blf[bt][1], blf[bt][3]);
                }
#pragma unroll
            for (int mt = 0; mt < 2; mt++)
#pragma unroll
                for (int bt = 0; bt < 2; bt++) {
                    mma16816(acc[mt][2 * bt],     alf[mt], bhf[bt][0], bhf[bt][2]);
                    mma16816(acc[mt][2 * bt + 1], alf[mt], bhf[bt][1], bhf[bt][3]);
                }
        }
        if (i + 2 < nc) issue(i + 2, (i + 2) % NSTG);
        CP_COMMIT();
    }

    // ---------------- epilogue ----------------
#pragma unroll
    for (int mt = 0; mt < 2; mt++) {
#pragma unroll
        for (int nt = 0; nt < 4; nt++) {
            const int col = n0 + wn + nt * 8 + (l & 3) * 2;
#pragma unroll
            for (int h = 0; h < 2; h++) {
                const int row = m0 + wm + mt * 16 + (l >> 2) + h * 8;
                float v0 = acc[mt][nt][h * 2], v1 = acc[mt][nt][h * 2 + 1];
                if (mode == 0) {
                    float2 o = make_float2(v0 * alpha, v1 * alpha);
                    *(float2*)(C + (long)bz * strideC + (long)row * ldc + col) = o;
                } else if (mode == 1) {
                    float x0 = v0 + __ldg(bias + col);
                    float x1 = v1 + __ldg(bias + col + 1);
                    __nv_bfloat16 h0, l0, h1, l1;
                    splitf(x0, h0, l0); splitf(x1, h1, l1);
                    __nv_bfloat162 hv; hv.x = h0; hv.y = h1;
                    __nv_bfloat162 lv; lv.x = l0; lv.y = l1;
                    *(__nv_bfloat162*)(Coh + (long)row * ldc + col) = hv;
                    *(__nv_bfloat162*)(Col + (long)row * ldc + col) = lv;
                } else if (mode == 2) {
                    float x0 = v0 + __ldg(bias + col);
                    float x1 = v1 + __ldg(bias + col + 1);
                    __nv_bfloat16 h0, l0, h1, l1;
                    splitf(x0, h0, l0); splitf(x1, h1, l1);
                    int b = row >> 11, s = row & (NS - 1);
                    long a0 = ((long)b * ND + col) * (long)NS + s;
                    Coh[a0] = h0;      Col[a0] = l0;
                    Coh[a0 + NS] = h1; Col[a0 + NS] = l1;
                } else {               // mode 4: bias + relu + resid
                    long a = (long)row * ldc + col;
                    float2 r2 = *(const float2*)(resid + a);
                    float2 o;
                    o.x = fmaxf(v0 + __ldg(bias + col), 0.f) + r2.x;
                    o.y = fmaxf(v1 + __ldg(bias + col + 1), 0.f) + r2.y;
                    *(float2*)(C + a) = o;
                }
            }
        }
    }
}

// ---------------- elementwise: split fp32 -> (bf16 hi, bf16 lo) ----------------
__global__ void split_bf(const float* __restrict__ x, __nv_bfloat16* __restrict__ h,
                         __nv_bfloat16* __restrict__ l, int n4)
{
    int i = blockIdx.x * 256 + threadIdx.x;
    if (i >= n4) return;
    float4 v = ((const float4*)x)[i];
    __nv_bfloat16 h0, l0, h1, l1, h2, l2, h3, l3;
    splitf(v.x, h0, l0); splitf(v.y, h1, l1);
    splitf(v.z, h2, l2); splitf(v.w, h3, l3);
    __nv_bfloat162 ha, hb, la, lb;
    ha.x = h0; ha.y = h1; hb.x = h2; hb.y = h3;
    la.x = l0; la.y = l1; lb.x = l2; lb.y = l3;
    ((__nv_bfloat162*)h)[2 * i] = ha; ((__nv_bfloat162*)h)[2 * i + 1] = hb;
    ((__nv_bfloat162*)l)[2 * i] = la; ((__nv_bfloat162*)l)[2 * i + 1] = lb;
}

// ---------------- masked row softmax -> split bf16 P ----------------
__global__ void softmax_rows(const float* __restrict__ sc, __nv_bfloat16* __restrict__ sch,
                             __nv_bfloat16* __restrict__ scl, const int* __restrict__ lens)
{
    __shared__ float red[256];
    const int t = threadIdx.x;
    const int q = blockIdx.x, b = blockIdx.y;
    const long base = ((long)b * NS + q) * NS;
    const float* row = sc + base;
    const int len = __ldg(lens + b);
    const int wlim = (len + BKE - 1) & ~(BKE - 1);   // PV never reads past this

    float m = -3.4e38f;
    for (int j = t; j < len; j += 256) m = fmaxf(m, row[j]);
    red[t] = m; __syncthreads();
    for (int s = 128; s > 0; s >>= 1) {
        if (t < s) red[t] = fmaxf(red[t], red[t + s]);
        __syncthreads();
    }
    m = red[0]; __syncthreads();

    float sum = 0.f;
    for (int j = t; j < len; j += 256) sum += __expf(row[j] - m);
    red[t] = sum; __syncthreads();
    for (int s = 128; s > 0; s >>= 1) {
        if (t < s) red[t] += red[t + s];
        __syncthreads();
    }
    const float inv = 1.0f / red[0];

    for (int j = t; j < wlim; j += 256) {
        float p = (j < len) ? __expf(row[j] - m) * inv : 0.f;
        __nv_bfloat16 h, lo;
        splitf(p, h, lo);
        sch[base + j] = h;
        scl[base + j] = lo;
    }
}

// ---------------- (optional resid) + LayerNorm (+optional bf16 split out) ----------------
__global__ void add_ln(const float* __restrict__ x, const float* __restrict__ res,
                       const float* __restrict__ g, const float* __restrict__ bt,
                       float* __restrict__ out, __nv_bfloat16* __restrict__ outh,
                       __nv_bfloat16* __restrict__ outl)
{
    __shared__ float r1[256], r2[256];
    const int t = threadIdx.x;
    const long row = blockIdx.x;

    float4 v = ((const float4*)(x + row * ND))[t];
    if (res) {
        float4 w = ((const float4*)(res + row * ND))[t];
        v.x += w.x; v.y += w.y; v.z += w.z; v.w += w.w;
    }
    float s  = v.x + v.y + v.z + v.w;
    float ss = v.x * v.x + v.y * v.y + v.z * v.z + v.w * v.w;
    r1[t] = s; r2[t] = ss; __syncthreads();
    for (int k = 128; k > 0; k >>= 1) {
        if (t < k) { r1[t] += r1[t + k]; r2[t] += r2[t + k]; }
        __syncthreads();
    }
    const float mean = r1[0] * (1.0f / ND);
    const float var  = r2[0] * (1.0f / ND) - mean * mean;
    const float inv  = rsqrtf(var + 1e-5f);

    float4 gg = ((const float4*)g)[t];
    float4 bb = ((const float4*)bt)[t];
    float4 o;
    o.x = (v.x - mean) * inv * gg.x + bb.x;
    o.y = (v.y - mean) * inv * gg.y + bb.y;
    o.z = (v.z - mean) * inv * gg.z + bb.z;
    o.w = (v.w - mean) * inv * gg.w + bb.w;
    if (out) ((float4*)(out + row * ND))[t] = o;
    if (outh) {
        __nv_bfloat16 h0, l0, h1, l1, h2, l2, h3, l3;
        splitf(o.x, h0, l0); splitf(o.y, h1, l1);
        splitf(o.z, h2, l2); splitf(o.w, h3, l3);
        __nv_bfloat162 ha, hb, la, lb;
        ha.x = h0; ha.y = h1; hb.x = h2; hb.y = h3;
        la.x = l0; la.y = l1; lb.x = l2; lb.y = l3;
        long p = row * (ND / 2) + 2 * t;
        ((__nv_bfloat162*)outh)[p] = ha; ((__nv_bfloat162*)outh)[p + 1] = hb;
        ((__nv_bfloat162*)outl)[p] = la; ((__nv_bfloat162*)outl)[p + 1] = lb;
    }
}

// ---------------- launch ----------------
extern "C" void kernel_launch(void* const* d_in, const int* in_sizes, int n_in,
                              void* d_out, int out_size)
{
    const float* seq  = (const float*)d_in[0];
    const int*   lens = (const int*)  d_in[1];
    const float* Wq = (const float*)d_in[2];
    const float* bq = (const float*)d_in[3];
    const float* Wk = (const float*)d_in[4];
    const float* bk = (const float*)d_in[5];
    const float* Wv = (const float*)d_in[6];
    const float* bv = (const float*)d_in[7];
    const float* Wo = (const float*)d_in[8];
    const float* bo = (const float*)d_in[9];
    const float* g1 = (const float*)d_in[10];
    const float* b1 = (const float*)d_in[11];
    const float* g2 = (const float*)d_in[12];
    const float* b2 = (const float*)d_in[13];
    float* out = (float*)d_out;

    static bool init_done = false;
    if (!init_done) {
        cudaFuncSetAttribute(gemm_bf3, cudaFuncAttributeMaxDynamicSharedMemorySize, GEMM_SMEM);
        init_done = true;
    }

    struct Ptrs {
        __nv_bfloat16 *seqh, *seql, *wqh, *wql, *wkh, *wkl, *wvh, *wvl, *woh, *wol;
        __nv_bfloat16 *qh, *ql, *kh, *kl, *vth, *vtl, *sch, *scl, *posth, *postl;
        float *sc, *attn, *post, *ffn;
    };
    static Ptrs P;
    static bool sym_done = false;
    if (!sym_done) {
        cudaGetSymbolAddress((void**)&P.seqh, g_seqh);   cudaGetSymbolAddress((void**)&P.seql, g_seql);
        cudaGetSymbolAddress((void**)&P.wqh,  g_wqh);    cudaGetSymbolAddress((void**)&P.wql,  g_wql);
        cudaGetSymbolAddress((void**)&P.wkh,  g_wkh);    cudaGetSymbolAddress((void**)&P.wkl,  g_wkl);
        cudaGetSymbolAddress((void**)&P.wvh,  g_wvh);    cudaGetSymbolAddress((void**)&P.wvl,  g_wvl);
        cudaGetSymbolAddress((void**)&P.woh,  g_woh);    cudaGetSymbolAddress((void**)&P.wol,  g_wol);
        cudaGetSymbolAddress((void**)&P.qh,   g_qh);     cudaGetSymbolAddress((void**)&P.ql,   g_ql);
        cudaGetSymbolAddress((void**)&P.kh,   g_kh);     cudaGetSymbolAddress((void**)&P.kl,   g_kl);
        cudaGetSymbolAddress((void**)&P.vth,  g_vth);    cudaGetSymbolAddress((void**)&P.vtl,  g_vtl);
        cudaGetSymbolAddress((void**)&P.sch,  g_sch);    cudaGetSymbolAddress((void**)&P.scl,  g_scl);
        cudaGetSymbolAddress((void**)&P.posth,g_posth);  cudaGetSymbolAddress((void**)&P.postl,g_postl);
        cudaGetSymbolAddress((void**)&P.sc,   g_sc);     cudaGetSymbolAddress((void**)&P.attn, g_attn);
        cudaGetSymbolAddress((void**)&P.post, g_post);   cudaGetSymbolAddress((void**)&P.ffn,  g_ffn);
        sym_done = true;
    }

    const long SD  = (long)NS * ND;
    const long SS2 = (long)NS * NS;

    // ---- split inputs to bf16 hi/lo ----
    split_bf<<<(NB * NS * ND) / 1024, 256>>>(seq, P.seqh, P.seql, NB * NS * ND / 4);
    split_bf<<<(ND * ND) / 1024, 256>>>(Wq, P.wqh, P.wql, ND * ND / 4);
    split_bf<<<(ND * ND) / 1024, 256>>>(Wk, P.wkh, P.wkl, ND * ND / 4);
    split_bf<<<(ND * ND) / 1024, 256>>>(Wv, P.wvh, P.wvl, ND * ND / 4);
    split_bf<<<(ND * ND) / 1024, 256>>>(Wo, P.woh, P.wol, ND * ND / 4);

    const dim3 blk(GT);
    const dim3 gproj(ND / 128, (NB * NS) / 128, 1);

    // Q projection (all rows); K, V projections skip masked-out rows
    gemm_bf3<<<gproj, blk, GEMM_SMEM>>>(P.seqh, P.seql, P.wqh, P.wql, ND, 0, 0,
        1, 1.f, bq, nullptr, nullptr, 0, ND, P.qh, P.ql, nullptr, 0);
    gemm_bf3<<<gproj, blk, GEMM_SMEM>>>(P.seqh, P.seql, P.wkh, P.wkl, ND, 0, 0,
        1, 1.f, bk, nullptr, nullptr, 0, ND, P.kh, P.kl, lens, 3);
    gemm_bf3<<<gproj, blk, GEMM_SMEM>>>(P.seqh, P.seql, P.wvh, P.wvl, ND, 0, 0,
        2, 1.f, bv, nullptr, nullptr, 0, ND, P.vth, P.vtl, lens, 3);

    // scores = Q K^T / 32 (masked n-tiles skipped)
    gemm_bf3<<<dim3(NS / 128, NS / 128, NB), blk, GEMM_SMEM>>>(
        P.qh, P.ql, P.kh, P.kl, ND, SD, SD,
        0, 1.0f / 32.0f, nullptr, nullptr, P.sc, SS2, NS, nullptr, nullptr, lens, 1);

    softmax_rows<<<dim3(NS, NB), 256>>>(P.sc, P.sch, P.scl, lens);

    // attn = P @ V (B-operand = V^T, K truncated at len)
    gemm_bf3<<<dim3(ND / 128, NS / 128, NB), blk, GEMM_SMEM>>>(
        P.sch, P.scl, P.vth, P.vtl, NS, SS2, SD,
        0, 1.f, nullptr, nullptr, P.attn, SD, ND, nullptr, nullptr, lens, 2);

    // post = LN(seq + attn), also split for FFN A-operand
    add_ln<<<NB * NS, 256>>>(P.attn, seq, g1, b1, P.post, P.posth, P.postl);

    // ffn = relu(post @ Wo^T + bo) + post
    gemm_bf3<<<gproj, blk, GEMM_SMEM>>>(P.posth, P.postl, P.woh, P.wol, ND, 0, 0,
        4, 1.f, bo, P.post, P.ffn, 0, ND, nullptr, nullptr, nullptr, 0);

    // out = LN(ffn)
    add_ln<<<NB * NS, 256>>>(P.ffn, nullptr, g2, b2, out, nullptr, nullptr);
}

// round 11
// speedup vs baseline: 3.0736x; 1.3341x over previous
#include <cuda_runtime.h>
#include <cuda_fp16.h>
#include <cstdint>

#define NB 8
#define NS 2048
#define ND 1024

// ---------------- scratch (device globals; raw-bit storage, no class types) ----
__device__ unsigned short g_seqh[NB*NS*ND], g_seql[NB*NS*ND];
__device__ unsigned short g_wqh[ND*ND], g_wkh[ND*ND], g_wvh[ND*ND], g_woh[ND*ND];
__device__ unsigned short g_qh[NB*NS*ND], g_ql[NB*NS*ND];
__device__ unsigned short g_kh[NB*NS*ND];                   // K single-rounded
__device__ unsigned short g_vth[NB*NS*ND];                  // V^T single: [B][D][S]
__device__ unsigned short g_sch[NB*NS*NS], g_scl[NB*NS*NS]; // split softmax P
__device__ unsigned short g_posth[NB*NS*ND], g_postl[NB*NS*ND];
__device__ float g_sc[NB*NS*NS];
__device__ float g_attn[NB*NS*ND];
__device__ float g_post[NB*NS*ND];
__device__ float g_ffn[NB*NS*ND];

// ---------------- helpers ----------------
__device__ __forceinline__ uint32_t smem_u32(const void* p) {
    uint32_t a;
    asm("{ .reg .u64 t; cvta.to.shared.u64 t, %1; cvt.u32.u64 %0, t; }" : "=r"(a) : "l"(p));
    return a;
}

#define CP_ASYNC16(s, g) \
    asm volatile("cp.async.cg.shared.global [%0], [%1], 16;" :: "r"(s), "l"(g) : "memory")
#define CP_COMMIT() asm volatile("cp.async.commit_group;" ::: "memory")
#define CP_WAIT1()  asm volatile("cp.async.wait_group 1;" ::: "memory")

__device__ __forceinline__ void ldmx4(uint32_t r[4], uint32_t a) {
    asm volatile("ldmatrix.sync.aligned.m8n8.x4.shared.b16 {%0,%1,%2,%3}, [%4];"
        : "=r"(r[0]), "=r"(r[1]), "=r"(r[2]), "=r"(r[3]) : "r"(a));
}

__device__ __forceinline__ void mma16816(float c[4], const uint32_t a[4],
                                         uint32_t b0, uint32_t b1) {
    asm volatile("mma.sync.aligned.m16n8k16.row.col.f32.f16.f16.f32 "
        "{%0,%1,%2,%3}, {%4,%5,%6,%7}, {%8,%9}, {%0,%1,%2,%3};"
        : "+f"(c[0]), "+f"(c[1]), "+f"(c[2]), "+f"(c[3])
        : "r"(a[0]), "r"(a[1]), "r"(a[2]), "r"(a[3]), "r"(b0), "r"(b1));
}

// fp16 hi/lo split as raw bits
__device__ __forceinline__ unsigned short h_hi(float x) {
    return __half_as_ushort(__float2half_rn(x));
}
__device__ __forceinline__ void h_split(float x, unsigned short& h, unsigned short& l) {
    __half hh = __float2half_rn(x);
    h = __half_as_ushort(hh);
    l = __half_as_ushort(__float2half_rn(x - __half2float(hh)));
}
__device__ __forceinline__ uint32_t pack2(unsigned short a, unsigned short b) {
    return (uint32_t)a | ((uint32_t)b << 16);
}

// ---------------- fp16 2-term GEMM (NT): C = alpha * A @ B^T ----------------
// A stored K-major as (hi,lo) fp16-bit pairs; B single-rounded fp16 bits.
// acc = Ah*Bh + Al*Bh (= A*Bh; dropped A*(B-Bh) ~ 2^-12 relative).
// 512 threads, 4x4 warp grid, 32x32 warp tile, 128x128x32 CTA tile.
// modes: 0 fp32*alpha; 1 split+bias; 5 single+bias; 6 transposed single+bias;
//        4 bias+relu+resid fp32.
// lenmode: 1 skip n-tiles >= len (scores); 2 truncate K at len (PV);
//          3 skip m-tiles whose in-batch row >= len (K/V projections).
#define BKE 32
#define TILE_B 8192          // 128 rows * 32 halves * 2B
#define STAGE_B (3*TILE_B)   // Ah, Al, Bh
#define NSTG 3
#define GEMM_SMEM (NSTG*STAGE_B)   // 73728
#define GT 512

#define SW(row, c) (((c) ^ ((row) >> 1)) & 3)

__global__ void __launch_bounds__(GT, 1) gemm_h2(
    const unsigned short* __restrict__ Ah, const unsigned short* __restrict__ Al,
    const unsigned short* __restrict__ Bh,
    int K, long sA, long sB,
    int mode, float alpha, const float* __restrict__ bias,
    const float* __restrict__ resid,
    float* __restrict__ C, long strideC, int ldc,
    unsigned short* __restrict__ Coh, unsigned short* __restrict__ Col,
    const int* __restrict__ lens, int lenmode)
{
    extern __shared__ char smem[];
    const int t = threadIdx.x, wid = t >> 5, l = t & 31;
    const int m0 = blockIdx.y * 128, n0 = blockIdx.x * 128, bz = blockIdx.z;

    int nc = K / BKE;
    if (lenmode == 1) { if (n0 >= __ldg(lens + bz)) return; }
    if (lenmode == 2) { int len = __ldg(lens + bz); int kk = (len + BKE - 1) & ~(BKE - 1); if (kk < K) nc = kk / BKE; }
    if (lenmode == 3) { if ((m0 & (NS - 1)) >= __ldg(lens + (m0 >> 11))) return; }

    const unsigned short* pAh = Ah + (long)bz * sA;
    const unsigned short* pAl = Al + (long)bz * sA;
    const unsigned short* pBh = Bh + (long)bz * sB;

    const uint32_t sb = smem_u32(smem);
    const int wm = (wid & 3) * 32, wn = (wid >> 2) * 32;   // 4x4 warp grid

    float acc[2][4][4];
#pragma unroll
    for (int i = 0; i < 2; i++)
#pragma unroll
        for (int j = 0; j < 4; j++)
#pragma unroll
            for (int e = 0; e < 4; e++) acc[i][j][e] = 0.f;

    auto issue = [&](int c, int s) {
        const long k0 = (long)c * BKE;
        const uint32_t stg = sb + (uint32_t)s * STAGE_B;
        int row = t >> 2, ch = t & 3;
        uint32_t off = (uint32_t)row * 64 + (SW(row, ch) << 4);
        long ga = (long)(m0 + row) * K + k0 + ch * 8;
        long gb = (long)(n0 + row) * K + k0 + ch * 8;
        CP_ASYNC16(stg + off,              (const void*)(pAh + ga));
        CP_ASYNC16(stg + TILE_B + off,     (const void*)(pAl + ga));
        CP_ASYNC16(stg + 2 * TILE_B + off, (const void*)(pBh + gb));
    };

    issue(0, 0); CP_COMMIT();
    if (nc > 1) issue(1, 1);
    CP_COMMIT();

    for (int i = 0; i < nc; i++) {
        CP_WAIT1();
        __syncthreads();
        const uint32_t stg = sb + (uint32_t)(i % NSTG) * STAGE_B;
#pragma unroll
        for (int sub = 0; sub < 2; sub++) {
            uint32_t ahf[2][4], alf[2][4], bhf[2][4];
            const int ch = sub * 2 + (l >> 4);
#pragma unroll
            for (int mt = 0; mt < 2; mt++) {
                int r = wm + mt * 16 + (l & 15);
                uint32_t off = (uint32_t)r * 64 + (SW(r, ch) << 4);
                ldmx4(ahf[mt], stg + off);
                ldmx4(alf[mt], stg + TILE_B + off);
            }
#pragma unroll
            for (int bt = 0; bt < 2; bt++) {
                int r = wn + bt * 16 + (l & 15);
                uint32_t off = (uint32_t)r * 64 + (SW(r, ch) << 4);
                ldmx4(bhf[bt], stg + 2 * TILE_B + off);
            }
            // term-outer: 8 independent MMAs per term
#pragma unroll
            for (int mt = 0; mt < 2; mt++)
#pragma unroll
                for (int bt = 0; bt < 2; bt++) {
                    mma16816(acc[mt][2 * bt],     ahf[mt], bhf[bt][0], bhf[bt][2]);
                    mma16816(acc[mt][2 * bt + 1], ahf[mt], bhf[bt][1], bhf[bt][3]);
                }
#pragma unroll
            for (int mt = 0; mt < 2; mt++)
#pragma unroll
                for (int bt = 0; bt < 2; bt++) {
                    mma16816(acc[mt][2 * bt],     alf[mt], bhf[bt][0], bhf[bt][2]);
                    mma16816(acc[mt][2 * bt + 1], alf[mt], bhf[bt][1], bhf[bt][3]);
                }
        }
        if (i + 2 < nc) issue(i + 2, (i + 2) % NSTG);
        CP_COMMIT();
    }

    // ---------------- epilogue ----------------
#pragma unroll
    for (int mt = 0; mt < 2; mt++) {
#pragma unroll
        for (int nt = 0; nt < 4; nt++) {
            const int col = n0 + wn + nt * 8 + (l & 3) * 2;
#pragma unroll
            for (int h = 0; h < 2; h++) {
                const int row = m0 + wm + mt * 16 + (l >> 2) + h * 8;
                float v0 = acc[mt][nt][h * 2], v1 = acc[mt][nt][h * 2 + 1];
                if (mode == 0) {
                    float2 o = make_float2(v0 * alpha, v1 * alpha);
                    *(float2*)(C + (long)bz * strideC + (long)row * ldc + col) = o;
                } else if (mode == 1) {            // Q: split+bias
                    float x0 = v0 + __ldg(bias + col);
                    float x1 = v1 + __ldg(bias + col + 1);
                    unsigned short h0, l0, h1, l1;
                    h_split(x0, h0, l0); h_split(x1, h1, l1);
                    *(uint32_t*)(Coh + (long)row * ldc + col) = pack2(h0, h1);
                    *(uint32_t*)(Col + (long)row * ldc + col) = pack2(l0, l1);
                } else if (mode == 5) {            // K: single+bias
                    *(uint32_t*)(Coh + (long)row * ldc + col) =
                        pack2(h_hi(v0 + __ldg(bias + col)), h_hi(v1 + __ldg(bias + col + 1)));
                } else if (mode == 6) {            // V: transposed single+bias
                    int b = row >> 11, s = row & (NS - 1);
                    long a0 = ((long)b * ND + col) * (long)NS + s;
                    Coh[a0]      = h_hi(v0 + __ldg(bias + col));
                    Coh[a0 + NS] = h_hi(v1 + __ldg(bias + col + 1));
                } else {                           // mode 4: bias + relu + resid
                    long a = (long)row * ldc + col;
                    float2 r2 = *(const float2*)(resid + a);
                    float2 o;
                    o.x = fmaxf(v0 + __ldg(bias + col), 0.f) + r2.x;
                    o.y = fmaxf(v1 + __ldg(bias + col + 1), 0.f) + r2.y;
                    *(float2*)(C + a) = o;
                }
            }
        }
    }
}

// ---------------- elementwise: split fp32 -> (hi, lo) fp16 bits ----------------
__global__ void split_h(const float* __restrict__ x, unsigned short* __restrict__ h,
                        unsigned short* __restrict__ l, int n4)
{
    int i = blockIdx.x * 256 + threadIdx.x;
    if (i >= n4) return;
    float4 v = ((const float4*)x)[i];
    unsigned short h0, l0, h1, l1, h2, l2, h3, l3;
    h_split(v.x, h0, l0); h_split(v.y, h1, l1);
    h_split(v.z, h2, l2); h_split(v.w, h3, l3);
    ((uint32_t*)h)[2 * i]     = pack2(h0, h1);
    ((uint32_t*)h)[2 * i + 1] = pack2(h2, h3);
    ((uint32_t*)l)[2 * i]     = pack2(l0, l1);
    ((uint32_t*)l)[2 * i + 1] = pack2(l2, l3);
}

// ---------------- elementwise: round fp32 -> fp16 bits ----------------
__global__ void round_h(const float* __restrict__ x, unsigned short* __restrict__ h, int n4)
{
    int i = blockIdx.x * 256 + threadIdx.x;
    if (i >= n4) return;
    float4 v = ((const float4*)x)[i];
    ((uint32_t*)h)[2 * i]     = pack2(h_hi(v.x), h_hi(v.y));
    ((uint32_t*)h)[2 * i + 1] = pack2(h_hi(v.z), h_hi(v.w));
}

// ---------------- masked row softmax -> split fp16 P ----------------
__global__ void softmax_rows(const float* __restrict__ sc, unsigned short* __restrict__ sch,
                             unsigned short* __restrict__ scl, const int* __restrict__ lens)
{
    __shared__ float red[256];
    const int t = threadIdx.x;
    const int q = blockIdx.x, b = blockIdx.y;
    const long base = ((long)b * NS + q) * NS;
    const float* row = sc + base;
    const int len = __ldg(lens + b);
    const int wlim = (len + BKE - 1) & ~(BKE - 1);   // PV never reads past this

    float m = -3.4e38f;
    for (int j = t; j < len; j += 256) m = fmaxf(m, row[j]);
    red[t] = m; __syncthreads();
    for (int s = 128; s > 0; s >>= 1) {
        if (t < s) red[t] = fmaxf(red[t], red[t + s]);
        __syncthreads();
    }
    m = red[0]; __syncthreads();

    float sum = 0.f;
    for (int j = t; j < len; j += 256) sum += __expf(row[j] - m);
    red[t] = sum; __syncthreads();
    for (int s = 128; s > 0; s >>= 1) {
        if (t < s) red[t] += red[t + s];
        __syncthreads();
    }
    const float inv = 1.0f / red[0];

    for (int j = t; j < wlim; j += 256) {
        float p = (j < len) ? __expf(row[j] - m) * inv : 0.f;
        unsigned short h, lo;
        h_split(p, h, lo);
        sch[base + j] = h;
        scl[base + j] = lo;
    }
}

// ---------------- (optional resid) + LayerNorm (+optional split out) ----------------
__global__ void add_ln(const float* __restrict__ x, const float* __restrict__ res,
                       const float* __restrict__ g, const float* __restrict__ bt,
                       float* __restrict__ out, unsigned short* __restrict__ outh,
                       unsigned short* __restrict__ outl)
{
    __shared__ float r1[256], r2[256];
    const int t = threadIdx.x;
    const long row = blockIdx.x;

    float4 v = ((const float4*)(x + row * ND))[t];
    if (res) {
        float4 w = ((const float4*)(res + row * ND))[t];
        v.x += w.x; v.y += w.y; v.z += w.z; v.w += w.w;
    }
    float s  = v.x + v.y + v.z + v.w;
    float ss = v.x * v.x + v.y * v.y + v.z * v.z + v.w * v.w;
    r1[t] = s; r2[t] = ss; __syncthreads();
    for (int k = 128; k > 0; k >>= 1) {
        if (t < k) { r1[t] += r1[t + k]; r2[t] += r2[t + k]; }
        __syncthreads();
    }
    const float mean = r1[0] * (1.0f / ND);
    const float var  = r2[0] * (1.0f / ND) - mean * mean;
    const float inv  = rsqrtf(var + 1e-5f);

    float4 gg = ((const float4*)g)[t];
    float4 bb = ((const float4*)bt)[t];
    float4 o;
    o.x = (v.x - mean) * inv * gg.x + bb.x;
    o.y = (v.y - mean) * inv * gg.y + bb.y;
    o.z = (v.z - mean) * inv * gg.z + bb.z;
    o.w = (v.w - mean) * inv * gg.w + bb.w;
    if (out) ((float4*)(out + row * ND))[t] = o;
    if (outh) {
        unsigned short h0, l0, h1, l1, h2, l2, h3, l3;
        h_split(o.x, h0, l0); h_split(o.y, h1, l1);
        h_split(o.z, h2, l2); h_split(o.w, h3, l3);
        long p = row * (ND / 2) + 2 * t;
        ((uint32_t*)outh)[p]     = pack2(h0, h1);
        ((uint32_t*)outh)[p + 1] = pack2(h2, h3);
        ((uint32_t*)outl)[p]     = pack2(l0, l1);
        ((uint32_t*)outl)[p + 1] = pack2(l2, l3);
    }
}

// ---------------- launch ----------------
extern "C" void kernel_launch(void* const* d_in, const int* in_sizes, int n_in,
                              void* d_out, int out_size)
{
    const float* seq  = (const float*)d_in[0];
    const int*   lens = (const int*)  d_in[1];
    const float* Wq = (const float*)d_in[2];
    const float* bq = (const float*)d_in[3];
    const float* Wk = (const float*)d_in[4];
    const float* bk = (const float*)d_in[5];
    const float* Wv = (const float*)d_in[6];
    const float* bv = (const float*)d_in[7];
    const float* Wo = (const float*)d_in[8];
    const float* bo = (const float*)d_in[9];
    const float* g1 = (const float*)d_in[10];
    const float* b1 = (const float*)d_in[11];
    const float* g2 = (const float*)d_in[12];
    const float* b2 = (const float*)d_in[13];
    float* out = (float*)d_out;

    static bool init_done = false;
    if (!init_done) {
        cudaFuncSetAttribute(gemm_h2, cudaFuncAttributeMaxDynamicSharedMemorySize, GEMM_SMEM);
        init_done = true;
    }

    struct Ptrs {
        unsigned short *seqh, *seql, *wqh, *wkh, *wvh, *woh;
        unsigned short *qh, *ql, *kh, *vth, *sch, *scl, *posth, *postl;
        float *sc, *attn, *post, *ffn;
    };
    static Ptrs P;
    static bool sym_done = false;
    if (!sym_done) {
        cudaGetSymbolAddress((void**)&P.seqh, g_seqh);   cudaGetSymbolAddress((void**)&P.seql, g_seql);
        cudaGetSymbolAddress((void**)&P.wqh,  g_wqh);    cudaGetSymbolAddress((void**)&P.wkh,  g_wkh);
        cudaGetSymbolAddress((void**)&P.wvh,  g_wvh);    cudaGetSymbolAddress((void**)&P.woh,  g_woh);
        cudaGetSymbolAddress((void**)&P.qh,   g_qh);     cudaGetSymbolAddress((void**)&P.ql,   g_ql);
        cudaGetSymbolAddress((void**)&P.kh,   g_kh);     cudaGetSymbolAddress((void**)&P.vth,  g_vth);
        cudaGetSymbolAddress((void**)&P.sch,  g_sch);    cudaGetSymbolAddress((void**)&P.scl,  g_scl);
        cudaGetSymbolAddress((void**)&P.posth,g_posth);  cudaGetSymbolAddress((void**)&P.postl,g_postl);
        cudaGetSymbolAddress((void**)&P.sc,   g_sc);     cudaGetSymbolAddress((void**)&P.attn, g_attn);
        cudaGetSymbolAddress((void**)&P.post, g_post);   cudaGetSymbolAddress((void**)&P.ffn,  g_ffn);
        sym_done = true;
    }

    const long SD  = (long)NS * ND;
    const long SS2 = (long)NS * NS;

    // ---- prepare operands ----
    split_h<<<(NB * NS * ND) / 1024, 256>>>(seq, P.seqh, P.seql, NB * NS * ND / 4);
    round_h<<<(ND * ND) / 1024, 256>>>(Wq, P.wqh, ND * ND / 4);
    round_h<<<(ND * ND) / 1024, 256>>>(Wk, P.wkh, ND * ND / 4);
    round_h<<<(ND * ND) / 1024, 256>>>(Wv, P.wvh, ND * ND / 4);
    round_h<<<(ND * ND) / 1024, 256>>>(Wo, P.woh, ND * ND / 4);

    const dim3 blk(GT);
    const dim3 gproj(ND / 128, (NB * NS) / 128, 1);

    // Q projection (split store); K (single), V (transposed single) skip masked rows
    gemm_h2<<<gproj, blk, GEMM_SMEM>>>(P.seqh, P.seql, P.wqh, ND, 0, 0,
        1, 1.f, bq, nullptr, nullptr, 0, ND, P.qh, P.ql, nullptr, 0);
    gemm_h2<<<gproj, blk, GEMM_SMEM>>>(P.seqh, P.seql, P.wkh, ND, 0, 0,
        5, 1.f, bk, nullptr, nullptr, 0, ND, P.kh, nullptr, lens, 3);
    gemm_h2<<<gproj, blk, GEMM_SMEM>>>(P.seqh, P.seql, P.wvh, ND, 0, 0,
        6, 1.f, bv, nullptr, nullptr, 0, ND, P.vth, nullptr, lens, 3);

    // scores = Q K^T / 32 (masked n-tiles skipped); A=Q split, B=K single
    gemm_h2<<<dim3(NS / 128, NS / 128, NB), blk, GEMM_SMEM>>>(
        P.qh, P.ql, P.kh, ND, SD, SD,
        0, 1.0f / 32.0f, nullptr, nullptr, P.sc, SS2, NS, nullptr, nullptr, lens, 1);

    softmax_rows<<<dim3(NS, NB), 256>>>(P.sc, P.sch, P.scl, lens);

    // attn = P @ V (A=P split, B=V^T single, K truncated at len)
    gemm_h2<<<dim3(ND / 128, NS / 128, NB), blk, GEMM_SMEM>>>(
        P.sch, P.scl, P.vth, NS, SS2, SD,
        0, 1.f, nullptr, nullptr, P.attn, SD, ND, nullptr, nullptr, lens, 2);

    // post = LN(seq + attn), also split for FFN A-operand
    add_ln<<<NB * NS, 256>>>(P.attn, seq, g1, b1, P.post, P.posth, P.postl);

    // ffn = relu(post @ Wo^T + bo) + post
    gemm_h2<<<gproj, blk, GEMM_SMEM>>>(P.posth, P.postl, P.woh, ND, 0, 0,
        4, 1.f, bo, P.post, P.ffn, 0, ND, nullptr, nullptr, nullptr, 0);

    // out = LN(ffn)
    add_ln<<<NB * NS, 256>>>(P.ffn, nullptr, g2, b2, out, nullptr, nullptr);
}

// round 12
// speedup vs baseline: 4.7395x; 1.5420x over previous
#include <cuda_runtime.h>
#include <cuda_fp16.h>
#include <cstdint>

#define NB 8
#define NS 2048
#define ND 1024

// ---------------- scratch (device globals; raw-bit storage, no class types) ----
__device__ unsigned short g_seqh[NB*NS*ND];
__device__ unsigned short g_wqh[ND*ND], g_wkh[ND*ND], g_wvh[ND*ND], g_woh[ND*ND];
__device__ unsigned short g_qh[NB*NS*ND];
__device__ unsigned short g_kh[NB*NS*ND];
__device__ unsigned short g_vth[NB*NS*ND];                  // V^T: [B][D][S]
__device__ unsigned short g_sch[NB*NS*NS];                  // softmax P (fp16)
__device__ unsigned short g_posth[NB*NS*ND];
__device__ float g_sc[NB*NS*NS];
__device__ float g_attn[NB*NS*ND];
__device__ float g_post[NB*NS*ND];
__device__ float g_ffn[NB*NS*ND];

// ---------------- helpers ----------------
__device__ __forceinline__ uint32_t smem_u32(const void* p) {
    uint32_t a;
    asm("{ .reg .u64 t; cvta.to.shared.u64 t, %1; cvt.u32.u64 %0, t; }" : "=r"(a) : "l"(p));
    return a;
}

#define CP_ASYNC16(s, g) \
    asm volatile("cp.async.cg.shared.global [%0], [%1], 16;" :: "r"(s), "l"(g) : "memory")
#define CP_COMMIT() asm volatile("cp.async.commit_group;" ::: "memory")
#define CP_WAIT1()  asm volatile("cp.async.wait_group 1;" ::: "memory")

__device__ __forceinline__ void ldmx4(uint32_t r[4], uint32_t a) {
    asm volatile("ldmatrix.sync.aligned.m8n8.x4.shared.b16 {%0,%1,%2,%3}, [%4];"
        : "=r"(r[0]), "=r"(r[1]), "=r"(r[2]), "=r"(r[3]) : "r"(a));
}

__device__ __forceinline__ void mma16816(float c[4], const uint32_t a[4],
                                         uint32_t b0, uint32_t b1) {
    asm volatile("mma.sync.aligned.m16n8k16.row.col.f32.f16.f16.f32 "
        "{%0,%1,%2,%3}, {%4,%5,%6,%7}, {%8,%9}, {%0,%1,%2,%3};"
        : "+f"(c[0]), "+f"(c[1]), "+f"(c[2]), "+f"(c[3])
        : "r"(a[0]), "r"(a[1]), "r"(a[2]), "r"(a[3]), "r"(b0), "r"(b1));
}

__device__ __forceinline__ unsigned short h_hi(float x) {
    return __half_as_ushort(__float2half_rn(x));
}
__device__ __forceinline__ uint32_t pack2(unsigned short a, unsigned short b) {
    return (uint32_t)a | ((uint32_t)b << 16);
}

// ---------------- single-fp16 GEMM (NT): C = alpha * A @ B^T ----------------
// A, B single-rounded fp16 bits, fp32 accumulate.
// 512 threads, 4x4 warp grid, 32x32 warp tile, 128x128x32 CTA tile.
// modes: 0 fp32*alpha; 5 single+bias fp16; 6 transposed single+bias fp16 ([B][D][S]);
//        4 bias+relu+resid fp32.
// lenmode: 1 skip n-tiles >= len (scores); 2 truncate K at len (PV);
//          3 skip m-tiles whose in-batch row >= len (K/V projections).
#define BKE 32
#define TILE_B 8192          // 128 rows * 32 halves * 2B
#define STAGE_B (2*TILE_B)   // A, B
#define NSTG 3
#define GEMM_SMEM (NSTG*STAGE_B)   // 49152
#define GT 512

#define SW(row, c) (((c) ^ ((row) >> 1)) & 3)

__global__ void __launch_bounds__(GT, 1) gemm_h1(
    const unsigned short* __restrict__ Ah,
    const unsigned short* __restrict__ Bh,
    int K, long sA, long sB,
    int mode, float alpha, const float* __restrict__ bias,
    const float* __restrict__ resid,
    float* __restrict__ C, long strideC, int ldc,
    unsigned short* __restrict__ Coh,
    const int* __restrict__ lens, int lenmode)
{
    extern __shared__ char smem[];
    const int t = threadIdx.x, wid = t >> 5, l = t & 31;
    const int m0 = blockIdx.y * 128, n0 = blockIdx.x * 128, bz = blockIdx.z;

    int nc = K / BKE;
    if (lenmode == 1) { if (n0 >= __ldg(lens + bz)) return; }
    if (lenmode == 2) { int len = __ldg(lens + bz); int kk = (len + BKE - 1) & ~(BKE - 1); if (kk < K) nc = kk / BKE; }
    if (lenmode == 3) { if ((m0 & (NS - 1)) >= __ldg(lens + (m0 >> 11))) return; }

    const unsigned short* pAh = Ah + (long)bz * sA;
    const unsigned short* pBh = Bh + (long)bz * sB;

    const uint32_t sb = smem_u32(smem);
    const int wm = (wid & 3) * 32, wn = (wid >> 2) * 32;   // 4x4 warp grid

    float acc[2][4][4];
#pragma unroll
    for (int i = 0; i < 2; i++)
#pragma unroll
        for (int j = 0; j < 4; j++)
#pragma unroll
            for (int e = 0; e < 4; e++) acc[i][j][e] = 0.f;

    auto issue = [&](int c, int s) {
        const long k0 = (long)c * BKE;
        const uint32_t stg = sb + (uint32_t)s * STAGE_B;
        int row = t >> 2, ch = t & 3;
        uint32_t off = (uint32_t)row * 64 + (SW(row, ch) << 4);
        long ga = (long)(m0 + row) * K + k0 + ch * 8;
        long gb = (long)(n0 + row) * K + k0 + ch * 8;
        CP_ASYNC16(stg + off,          (const void*)(pAh + ga));
        CP_ASYNC16(stg + TILE_B + off, (const void*)(pBh + gb));
    };

    issue(0, 0); CP_COMMIT();
    if (nc > 1) issue(1, 1);
    CP_COMMIT();

    for (int i = 0; i < nc; i++) {
        CP_WAIT1();
        __syncthreads();
        const uint32_t stg = sb + (uint32_t)(i % NSTG) * STAGE_B;
#pragma unroll
        for (int sub = 0; sub < 2; sub++) {
            uint32_t ahf[2][4], bhf[2][4];
            const int ch = sub * 2 + (l >> 4);
#pragma unroll
            for (int mt = 0; mt < 2; mt++) {
                int r = wm + mt * 16 + (l & 15);
                uint32_t off = (uint32_t)r * 64 + (SW(r, ch) << 4);
                ldmx4(ahf[mt], stg + off);
            }
#pragma unroll
            for (int bt = 0; bt < 2; bt++) {
                int r = wn + bt * 16 + (l & 15);
                uint32_t off = (uint32_t)r * 64 + (SW(r, ch) << 4);
                ldmx4(bhf[bt], stg + TILE_B + off);
            }
#pragma unroll
            for (int mt = 0; mt < 2; mt++)
#pragma unroll
                for (int bt = 0; bt < 2; bt++) {
                    mma16816(acc[mt][2 * bt],     ahf[mt], bhf[bt][0], bhf[bt][2]);
                    mma16816(acc[mt][2 * bt + 1], ahf[mt], bhf[bt][1], bhf[bt][3]);
                }
        }
        if (i + 2 < nc) issue(i + 2, (i + 2) % NSTG);
        CP_COMMIT();
    }

    // ---------------- epilogue ----------------
#pragma unroll
    for (int mt = 0; mt < 2; mt++) {
#pragma unroll
        for (int nt = 0; nt < 4; nt++) {
            const int col = n0 + wn + nt * 8 + (l & 3) * 2;
#pragma unroll
            for (int h = 0; h < 2; h++) {
                const int row = m0 + wm + mt * 16 + (l >> 2) + h * 8;
                float v0 = acc[mt][nt][h * 2], v1 = acc[mt][nt][h * 2 + 1];
                if (mode == 0) {
                    float2 o = make_float2(v0 * alpha, v1 * alpha);
                    *(float2*)(C + (long)bz * strideC + (long)row * ldc + col) = o;
                } else if (mode == 5) {            // single+bias fp16
                    *(uint32_t*)(Coh + (long)row * ldc + col) =
                        pack2(h_hi(v0 + __ldg(bias + col)), h_hi(v1 + __ldg(bias + col + 1)));
                } else if (mode == 6) {            // transposed single+bias fp16
                    int b = row >> 11, s = row & (NS - 1);
                    long a0 = ((long)b * ND + col) * (long)NS + s;
                    Coh[a0]      = h_hi(v0 + __ldg(bias + col));
                    Coh[a0 + NS] = h_hi(v1 + __ldg(bias + col + 1));
                } else {                           // mode 4: bias + relu + resid
                    long a = (long)row * ldc + col;
                    float2 r2 = *(const float2*)(resid + a);
                    float2 o;
                    o.x = fmaxf(v0 + __ldg(bias + col), 0.f) + r2.x;
                    o.y = fmaxf(v1 + __ldg(bias + col + 1), 0.f) + r2.y;
                    *(float2*)(C + a) = o;
                }
            }
        }
    }
}

// ---------------- elementwise: round fp32 -> fp16 bits ----------------
__global__ void round_h(const float* __restrict__ x, unsigned short* __restrict__ h, int n4)
{
    int i = blockIdx.x * 256 + threadIdx.x;
    if (i >= n4) return;
    float4 v = ((const float4*)x)[i];
    ((uint32_t*)h)[2 * i]     = pack2(h_hi(v.x), h_hi(v.y));
    ((uint32_t*)h)[2 * i + 1] = pack2(h_hi(v.z), h_hi(v.w));
}

// ---------------- masked row softmax -> fp16 P ----------------
__global__ void softmax_rows(const float* __restrict__ sc, unsigned short* __restrict__ sch,
                             const int* __restrict__ lens)
{
    __shared__ float red[256];
    const int t = threadIdx.x;
    const int q = blockIdx.x, b = blockIdx.y;
    const long base = ((long)b * NS + q) * NS;
    const float* row = sc + base;
    const int len = __ldg(lens + b);
    const int wlim = (len + BKE - 1) & ~(BKE - 1);   // PV never reads past this

    float m = -3.4e38f;
    for (int j = t; j < len; j += 256) m = fmaxf(m, row[j]);
    red[t] = m; __syncthreads();
    for (int s = 128; s > 0; s >>= 1) {
        if (t < s) red[t] = fmaxf(red[t], red[t + s]);
        __syncthreads();
    }
    m = red[0]; __syncthreads();

    float sum = 0.f;
    for (int j = t; j < len; j += 256) sum += __expf(row[j] - m);
    red[t] = sum; __syncthreads();
    for (int s = 128; s > 0; s >>= 1) {
        if (t < s) red[t] += red[t + s];
        __syncthreads();
    }
    const float inv = 1.0f / red[0];

    for (int j = t; j < wlim; j += 256) {
        float p = (j < len) ? __expf(row[j] - m) * inv : 0.f;
        sch[base + j] = h_hi(p);
    }
}

// ---------------- (optional resid) + LayerNorm (+optional fp16 out) ----------------
__global__ void add_ln(const float* __restrict__ x, const float* __restrict__ res,
                       const float* __restrict__ g, const float* __restrict__ bt,
                       float* __restrict__ out, unsigned short* __restrict__ outh)
{
    __shared__ float r1[256], r2[256];
    const int t = threadIdx.x;
    const long row = blockIdx.x;

    float4 v = ((const float4*)(x + row * ND))[t];
    if (res) {
        float4 w = ((const float4*)(res + row * ND))[t];
        v.x += w.x; v.y += w.y; v.z += w.z; v.w += w.w;
    }
    float s  = v.x + v.y + v.z + v.w;
    float ss = v.x * v.x + v.y * v.y + v.z * v.z + v.w * v.w;
    r1[t] = s; r2[t] = ss; __syncthreads();
    for (int k = 128; k > 0; k >>= 1) {
        if (t < k) { r1[t] += r1[t + k]; r2[t] += r2[t + k]; }
        __syncthreads();
    }
    const float mean = r1[0] * (1.0f / ND);
    const float var  = r2[0] * (1.0f / ND) - mean * mean;
    const float inv  = rsqrtf(var + 1e-5f);

    float4 gg = ((const float4*)g)[t];
    float4 bb = ((const float4*)bt)[t];
    float4 o;
    o.x = (v.x - mean) * inv * gg.x + bb.x;
    o.y = (v.y - mean) * inv * gg.y + bb.y;
    o.z = (v.z - mean) * inv * gg.z + bb.z;
    o.w = (v.w - mean) * inv * gg.w + bb.w;
    if (out) ((float4*)(out + row * ND))[t] = o;
    if (outh) {
        long p = row * (ND / 2) + 2 * t;
        ((uint32_t*)outh)[p]     = pack2(h_hi(o.x), h_hi(o.y));
        ((uint32_t*)outh)[p + 1] = pack2(h_hi(o.z), h_hi(o.w));
    }
}

// ---------------- launch ----------------
extern "C" void kernel_launch(void* const* d_in, const int* in_sizes, int n_in,
                              void* d_out, int out_size)
{
    const float* seq  = (const float*)d_in[0];
    const int*   lens = (const int*)  d_in[1];
    const float* Wq = (const float*)d_in[2];
    const float* bq = (const float*)d_in[3];
    const float* Wk = (const float*)d_in[4];
    const float* bk = (const float*)d_in[5];
    const float* Wv = (const float*)d_in[6];
    const float* bv = (const float*)d_in[7];
    const float* Wo = (const float*)d_in[8];
    const float* bo = (const float*)d_in[9];
    const float* g1 = (const float*)d_in[10];
    const float* b1 = (const float*)d_in[11];
    const float* g2 = (const float*)d_in[12];
    const float* b2 = (const float*)d_in[13];
    float* out = (float*)d_out;

    static bool init_done = false;
    if (!init_done) {
        cudaFuncSetAttribute(gemm_h1, cudaFuncAttributeMaxDynamicSharedMemorySize, GEMM_SMEM);
        init_done = true;
    }

    struct Ptrs {
        unsigned short *seqh, *wqh, *wkh, *wvh, *woh;
        unsigned short *qh, *kh, *vth, *sch, *posth;
        float *sc, *attn, *post, *ffn;
    };
    static Ptrs P;
    static bool sym_done = false;
    if (!sym_done) {
        cudaGetSymbolAddress((void**)&P.seqh, g_seqh);
        cudaGetSymbolAddress((void**)&P.wqh,  g_wqh);    cudaGetSymbolAddress((void**)&P.wkh,  g_wkh);
        cudaGetSymbolAddress((void**)&P.wvh,  g_wvh);    cudaGetSymbolAddress((void**)&P.woh,  g_woh);
        cudaGetSymbolAddress((void**)&P.qh,   g_qh);     cudaGetSymbolAddress((void**)&P.kh,   g_kh);
        cudaGetSymbolAddress((void**)&P.vth,  g_vth);    cudaGetSymbolAddress((void**)&P.sch,  g_sch);
        cudaGetSymbolAddress((void**)&P.posth,g_posth);
        cudaGetSymbolAddress((void**)&P.sc,   g_sc);     cudaGetSymbolAddress((void**)&P.attn, g_attn);
        cudaGetSymbolAddress((void**)&P.post, g_post);   cudaGetSymbolAddress((void**)&P.ffn,  g_ffn);
        sym_done = true;
    }

    const long SD  = (long)NS * ND;
    const long SS2 = (long)NS * NS;

    // ---- prepare operands (single fp16 round) ----
    round_h<<<(NB * NS * ND) / 1024, 256>>>(seq, P.seqh, NB * NS * ND / 4);
    round_h<<<(ND * ND) / 1024, 256>>>(Wq, P.wqh, ND * ND / 4);
    round_h<<<(ND * ND) / 1024, 256>>>(Wk, P.wkh, ND * ND / 4);
    round_h<<<(ND * ND) / 1024, 256>>>(Wv, P.wvh, ND * ND / 4);
    round_h<<<(ND * ND) / 1024, 256>>>(Wo, P.woh, ND * ND / 4);

    const dim3 blk(GT);
    const dim3 gproj(ND / 128, (NB * NS) / 128, 1);

    // Q projection; K, V projections skip masked-out rows
    gemm_h1<<<gproj, blk, GEMM_SMEM>>>(P.seqh, P.wqh, ND, 0, 0,
        5, 1.f, bq, nullptr, nullptr, 0, ND, P.qh, nullptr, 0);
    gemm_h1<<<gproj, blk, GEMM_SMEM>>>(P.seqh, P.wkh, ND, 0, 0,
        5, 1.f, bk, nullptr, nullptr, 0, ND, P.kh, lens, 3);
    gemm_h1<<<gproj, blk, GEMM_SMEM>>>(P.seqh, P.wvh, ND, 0, 0,
        6, 1.f, bv, nullptr, nullptr, 0, ND, P.vth, lens, 3);

    // scores = Q K^T / 32 (masked n-tiles skipped)
    gemm_h1<<<dim3(NS / 128, NS / 128, NB), blk, GEMM_SMEM>>>(
        P.qh, P.kh, ND, SD, SD,
        0, 1.0f / 32.0f, nullptr, nullptr, P.sc, SS2, NS, nullptr, lens, 1);

    softmax_rows<<<dim3(NS, NB), 256>>>(P.sc, P.sch, lens);

    // attn = P @ V (B-operand = V^T, K truncated at len)
    gemm_h1<<<dim3(ND / 128, NS / 128, NB), blk, GEMM_SMEM>>>(
        P.sch, P.vth, NS, SS2, SD,
        0, 1.f, nullptr, nullptr, P.attn, SD, ND, nullptr, lens, 2);

    // post = LN(seq + attn), also fp16 for FFN A-operand
    add_ln<<<NB * NS, 256>>>(P.attn, seq, g1, b1, P.post, P.posth);

    // ffn = relu(post @ Wo^T + bo) + post
    gemm_h1<<<gproj, blk, GEMM_SMEM>>>(P.posth, P.woh, ND, 0, 0,
        4, 1.f, bo, P.post, P.ffn, 0, ND, nullptr, nullptr, 0);

    // out = LN(ffn)
    add_ln<<<NB * NS, 256>>>(P.ffn, nullptr, g2, b2, out, nullptr);
}

// round 13
// speedup vs baseline: 5.3865x; 1.1365x over previous
#include <cuda_runtime.h>
#include <cuda_fp16.h>
#include <cstdint>

#define NB 8
#define NS 2048
#define ND 1024

// ---------------- scratch (device globals; raw-bit storage, no class types) ----
__device__ unsigned short g_seqh[NB*NS*ND];
__device__ unsigned short g_wqh[ND*ND], g_wkh[ND*ND], g_wvh[ND*ND], g_woh[ND*ND];
__device__ unsigned short g_qh[NB*NS*ND];
__device__ unsigned short g_kh[NB*NS*ND];
__device__ unsigned short g_vth[NB*NS*ND];                  // V^T: [B][D][S]
__device__ unsigned short g_sch[NB*NS*NS];                  // softmax P (fp16)
__device__ unsigned short g_posth[NB*NS*ND];                // post (fp16 only)
__device__ float g_sc[NB*NS*NS];
__device__ float g_attn[NB*NS*ND];
__device__ float g_ffn[NB*NS*ND];

// ---------------- helpers ----------------
__device__ __forceinline__ uint32_t smem_u32(const void* p) {
    uint32_t a;
    asm("{ .reg .u64 t; cvta.to.shared.u64 t, %1; cvt.u32.u64 %0, t; }" : "=r"(a) : "l"(p));
    return a;
}

#define CP_ASYNC16(s, g) \
    asm volatile("cp.async.cg.shared.global [%0], [%1], 16;" :: "r"(s), "l"(g) : "memory")
#define CP_COMMIT() asm volatile("cp.async.commit_group;" ::: "memory")
#define CP_WAIT1()  asm volatile("cp.async.wait_group 1;" ::: "memory")

__device__ __forceinline__ void ldmx4(uint32_t r[4], uint32_t a) {
    asm volatile("ldmatrix.sync.aligned.m8n8.x4.shared.b16 {%0,%1,%2,%3}, [%4];"
        : "=r"(r[0]), "=r"(r[1]), "=r"(r[2]), "=r"(r[3]) : "r"(a));
}

__device__ __forceinline__ void mma16816(float c[4], const uint32_t a[4],
                                         uint32_t b0, uint32_t b1) {
    asm volatile("mma.sync.aligned.m16n8k16.row.col.f32.f16.f16.f32 "
        "{%0,%1,%2,%3}, {%4,%5,%6,%7}, {%8,%9}, {%0,%1,%2,%3};"
        : "+f"(c[0]), "+f"(c[1]), "+f"(c[2]), "+f"(c[3])
        : "r"(a[0]), "r"(a[1]), "r"(a[2]), "r"(a[3]), "r"(b0), "r"(b1));
}

__device__ __forceinline__ unsigned short h_hi(float x) {
    return __half_as_ushort(__float2half_rn(x));
}
__device__ __forceinline__ uint32_t pack2(unsigned short a, unsigned short b) {
    return (uint32_t)a | ((uint32_t)b << 16);
}
__device__ __forceinline__ float h2f(unsigned short u) {
    return __half2float(__ushort_as_half(u));
}

// ---------------- single-fp16 GEMM (NT): C = alpha * A @ B^T ----------------
// A, B fp16 bits, fp32 accumulate. 512 threads, 4x4 warp grid, 32x32 warp tile,
// 128x128x64 CTA tile (BKE=64 halves sync overhead vs 32).
// modes: 0 fp32*alpha; 5 single+bias fp16; 6 transposed single+bias fp16 ([B][D][S]);
//        4 bias+relu+(fp16 resid via Coh) fp32 out.
// lenmode: 1 skip n-tiles >= len (scores); 2 truncate K at len (PV);
//          3 skip m-tiles whose in-batch row >= len (K/V projections).
#define BKE 64
#define TILE_B 16384         // 128 rows * 64 halves * 2B
#define STAGE_B (2*TILE_B)   // A, B
#define NSTG 3
#define GEMM_SMEM (NSTG*STAGE_B)   // 98304
#define GT 512

#define SW8(row, c) (((c) ^ (row)) & 7)

__global__ void __launch_bounds__(GT, 1) gemm_h1(
    const unsigned short* __restrict__ Ah,
    const unsigned short* __restrict__ Bh,
    int K, long sA, long sB,
    int mode, float alpha, const float* __restrict__ bias,
    float* __restrict__ C, long strideC, int ldc,
    unsigned short* __restrict__ Coh,
    const int* __restrict__ lens, int lenmode)
{
    extern __shared__ char smem[];
    const int t = threadIdx.x, wid = t >> 5, l = t & 31;
    const int m0 = blockIdx.y * 128, n0 = blockIdx.x * 128, bz = blockIdx.z;

    int nc = K / BKE;
    if (lenmode == 1) { if (n0 >= __ldg(lens + bz)) return; }
    if (lenmode == 2) { int len = __ldg(lens + bz); int kk = (len + BKE - 1) & ~(BKE - 1); if (kk < K) nc = kk / BKE; }
    if (lenmode == 3) { if ((m0 & (NS - 1)) >= __ldg(lens + (m0 >> 11))) return; }

    const unsigned short* pAh = Ah + (long)bz * sA;
    const unsigned short* pBh = Bh + (long)bz * sB;

    const uint32_t sb = smem_u32(smem);
    const int wm = (wid & 3) * 32, wn = (wid >> 2) * 32;   // 4x4 warp grid

    float acc[2][4][4];
#pragma unroll
    for (int i = 0; i < 2; i++)
#pragma unroll
        for (int j = 0; j < 4; j++)
#pragma unroll
            for (int e = 0; e < 4; e++) acc[i][j][e] = 0.f;

    auto issue = [&](int c, int s) {
        const long k0 = (long)c * BKE;
        const uint32_t stg = sb + (uint32_t)s * STAGE_B;
#pragma unroll
        for (int j = 0; j < 2; j++) {
            int idx = t + j * GT;
            int row = idx >> 3, ch = idx & 7;          // 128-B rows, 8 x 16-B chunks
            uint32_t off = (uint32_t)row * 128 + (SW8(row, ch) << 4);
            long ga = (long)(m0 + row) * K + k0 + ch * 8;
            long gb = (long)(n0 + row) * K + k0 + ch * 8;
            CP_ASYNC16(stg + off,          (const void*)(pAh + ga));
            CP_ASYNC16(stg + TILE_B + off, (const void*)(pBh + gb));
        }
    };

    issue(0, 0); CP_COMMIT();
    if (nc > 1) issue(1, 1);
    CP_COMMIT();

    for (int i = 0; i < nc; i++) {
        CP_WAIT1();
        __syncthreads();
        const uint32_t stg = sb + (uint32_t)(i % NSTG) * STAGE_B;
#pragma unroll
        for (int sub = 0; sub < 4; sub++) {
            uint32_t ahf[2][4], bhf[2][4];
            const int ch = sub * 2 + (l >> 4);
#pragma unroll
            for (int mt = 0; mt < 2; mt++) {
                int r = wm + mt * 16 + (l & 15);
                uint32_t off = (uint32_t)r * 128 + (SW8(r, ch) << 4);
                ldmx4(ahf[mt], stg + off);
            }
#pragma unroll
            for (int bt = 0; bt < 2; bt++) {
                int r = wn + bt * 16 + (l & 15);
                uint32_t off = (uint32_t)r * 128 + (SW8(r, ch) << 4);
                ldmx4(bhf[bt], stg + TILE_B + off);
            }
#pragma unroll
            for (int mt = 0; mt < 2; mt++)
#pragma unroll
                for (int bt = 0; bt < 2; bt++) {
                    mma16816(acc[mt][2 * bt],     ahf[mt], bhf[bt][0], bhf[bt][2]);
                    mma16816(acc[mt][2 * bt + 1], ahf[mt], bhf[bt][1], bhf[bt][3]);
                }
        }
        if (i + 2 < nc) issue(i + 2, (i + 2) % NSTG);
        CP_COMMIT();
    }

    // ---------------- epilogue ----------------
#pragma unroll
    for (int mt = 0; mt < 2; mt++) {
#pragma unroll
        for (int nt = 0; nt < 4; nt++) {
            const int col = n0 + wn + nt * 8 + (l & 3) * 2;
#pragma unroll
            for (int h = 0; h < 2; h++) {
                const int row = m0 + wm + mt * 16 + (l >> 2) + h * 8;
                float v0 = acc[mt][nt][h * 2], v1 = acc[mt][nt][h * 2 + 1];
                if (mode == 0) {
                    float2 o = make_float2(v0 * alpha, v1 * alpha);
                    *(float2*)(C + (long)bz * strideC + (long)row * ldc + col) = o;
                } else if (mode == 5) {            // single+bias fp16
                    *(uint32_t*)(Coh + (long)row * ldc + col) =
                        pack2(h_hi(v0 + __ldg(bias + col)), h_hi(v1 + __ldg(bias + col + 1)));
                } else if (mode == 6) {            // transposed single+bias fp16
                    int b = row >> 11, s = row & (NS - 1);
                    long a0 = ((long)b * ND + col) * (long)NS + s;
                    Coh[a0]      = h_hi(v0 + __ldg(bias + col));
                    Coh[a0 + NS] = h_hi(v1 + __ldg(bias + col + 1));
                } else {                           // mode 4: bias + relu + fp16 resid
                    long a = (long)row * ldc + col;
                    uint32_t rr = *(const uint32_t*)(Coh + a);
                    float2 o;
                    o.x = fmaxf(v0 + __ldg(bias + col), 0.f) + h2f((unsigned short)(rr & 0xFFFF));
                    o.y = fmaxf(v1 + __ldg(bias + col + 1), 0.f) + h2f((unsigned short)(rr >> 16));
                    *(float2*)(C + a) = o;
                }
            }
        }
    }
}

// ---------------- elementwise: round fp32 -> fp16 bits ----------------
__global__ void round_h(const float* __restrict__ x, unsigned short* __restrict__ h, int n4)
{
    int i = blockIdx.x * 256 + threadIdx.x;
    if (i >= n4) return;
    float4 v = ((const float4*)x)[i];
    ((uint32_t*)h)[2 * i]     = pack2(h_hi(v.x), h_hi(v.y));
    ((uint32_t*)h)[2 * i + 1] = pack2(h_hi(v.z), h_hi(v.w));
}

// ---------------- masked row softmax -> fp16 P ----------------
__global__ void softmax_rows(const float* __restrict__ sc, unsigned short* __restrict__ sch,
                             const int* __restrict__ lens)
{
    __shared__ float red[256];
    const int t = threadIdx.x;
    const int q = blockIdx.x, b = blockIdx.y;
    const long base = ((long)b * NS + q) * NS;
    const float* row = sc + base;
    const int len = __ldg(lens + b);
    const int wlim = (len + BKE - 1) & ~(BKE - 1);   // PV never reads past this

    float m = -3.4e38f;
    for (int j = t; j < len; j += 256) m = fmaxf(m, row[j]);
    red[t] = m; __syncthreads();
    for (int s = 128; s > 0; s >>= 1) {
        if (t < s) red[t] = fmaxf(red[t], red[t + s]);
        __syncthreads();
    }
    m = red[0]; __syncthreads();

    float sum = 0.f;
    for (int j = t; j < len; j += 256) sum += __expf(row[j] - m);
    red[t] = sum; __syncthreads();
    for (int s = 128; s > 0; s >>= 1) {
        if (t < s) red[t] += red[t + s];
        __syncthreads();
    }
    const float inv = 1.0f / red[0];

    for (int j = t; j < wlim; j += 256) {
        float p = (j < len) ? __expf(row[j] - m) * inv : 0.f;
        sch[base + j] = h_hi(p);
    }
}

// ---------------- (optional resid) + LayerNorm (fp32 and/or fp16 out) ----------------
__global__ void add_ln(const float* __restrict__ x, const float* __restrict__ res,
                       const float* __restrict__ g, const float* __restrict__ bt,
                       float* __restrict__ out, unsigned short* __restrict__ outh)
{
    __shared__ float r1[256], r2[256];
    const int t = threadIdx.x;
    const long row = blockIdx.x;

    float4 v = ((const float4*)(x + row * ND))[t];
    if (res) {
        float4 w = ((const float4*)(res + row * ND))[t];
        v.x += w.x; v.y += w.y; v.z += w.z; v.w += w.w;
    }
    float s  = v.x + v.y + v.z + v.w;
    float ss = v.x * v.x + v.y * v.y + v.z * v.z + v.w * v.w;
    r1[t] = s; r2[t] = ss; __syncthreads();
    for (int k = 128; k > 0; k >>= 1) {
        if (t < k) { r1[t] += r1[t + k]; r2[t] += r2[t + k]; }
        __syncthreads();
    }
    const float mean = r1[0] * (1.0f / ND);
    const float var  = r2[0] * (1.0f / ND) - mean * mean;
    const float inv  = rsqrtf(var + 1e-5f);

    float4 gg = ((const float4*)g)[t];
    float4 bb = ((const float4*)bt)[t];
    float4 o;
    o.x = (v.x - mean) * inv * gg.x + bb.x;
    o.y = (v.y - mean) * inv * gg.y + bb.y;
    o.z = (v.z - mean) * inv * gg.z + bb.z;
    o.w = (v.w - mean) * inv * gg.w + bb.w;
    if (out) ((float4*)(out + row * ND))[t] = o;
    if (outh) {
        long p = row * (ND / 2) + 2 * t;
        ((uint32_t*)outh)[p]     = pack2(h_hi(o.x), h_hi(o.y));
        ((uint32_t*)outh)[p + 1] = pack2(h_hi(o.z), h_hi(o.w));
    }
}

// ---------------- launch ----------------
extern "C" void kernel_launch(void* const* d_in, const int* in_sizes, int n_in,
                              void* d_out, int out_size)
{
    const float* seq  = (const float*)d_in[0];
    const int*   lens = (const int*)  d_in[1];
    const float* Wq = (const float*)d_in[2];
    const float* bq = (const float*)d_in[3];
    const float* Wk = (const float*)d_in[4];
    const float* bk = (const float*)d_in[5];
    const float* Wv = (const float*)d_in[6];
    const float* bv = (const float*)d_in[7];
    const float* Wo = (const float*)d_in[8];
    const float* bo = (const float*)d_in[9];
    const float* g1 = (const float*)d_in[10];
    const float* b1 = (const float*)d_in[11];
    const float* g2 = (const float*)d_in[12];
    const float* b2 = (const float*)d_in[13];
    float* out = (float*)d_out;

    static bool init_done = false;
    if (!init_done) {
        cudaFuncSetAttribute(gemm_h1, cudaFuncAttributeMaxDynamicSharedMemorySize, GEMM_SMEM);
        init_done = true;
    }

    struct Ptrs {
        unsigned short *seqh, *wqh, *wkh, *wvh, *woh;
        unsigned short *qh, *kh, *vth, *sch, *posth;
        float *sc, *attn, *ffn;
    };
    static Ptrs P;
    static bool sym_done = false;
    if (!sym_done) {
        cudaGetSymbolAddress((void**)&P.seqh, g_seqh);
        cudaGetSymbolAddress((void**)&P.wqh,  g_wqh);    cudaGetSymbolAddress((void**)&P.wkh,  g_wkh);
        cudaGetSymbolAddress((void**)&P.wvh,  g_wvh);    cudaGetSymbolAddress((void**)&P.woh,  g_woh);
        cudaGetSymbolAddress((void**)&P.qh,   g_qh);     cudaGetSymbolAddress((void**)&P.kh,   g_kh);
        cudaGetSymbolAddress((void**)&P.vth,  g_vth);    cudaGetSymbolAddress((void**)&P.sch,  g_sch);
        cudaGetSymbolAddress((void**)&P.posth,g_posth);
        cudaGetSymbolAddress((void**)&P.sc,   g_sc);     cudaGetSymbolAddress((void**)&P.attn, g_attn);
        cudaGetSymbolAddress((void**)&P.ffn,  g_ffn);
        sym_done = true;
    }

    const long SD  = (long)NS * ND;
    const long SS2 = (long)NS * NS;

    // ---- prepare operands (single fp16 round) ----
    round_h<<<(NB * NS * ND) / 1024, 256>>>(seq, P.seqh, NB * NS * ND / 4);
    round_h<<<(ND * ND) / 1024, 256>>>(Wq, P.wqh, ND * ND / 4);
    round_h<<<(ND * ND) / 1024, 256>>>(Wk, P.wkh, ND * ND / 4);
    round_h<<<(ND * ND) / 1024, 256>>>(Wv, P.wvh, ND * ND / 4);
    round_h<<<(ND * ND) / 1024, 256>>>(Wo, P.woh, ND * ND / 4);

    const dim3 blk(GT);
    const dim3 gproj(ND / 128, (NB * NS) / 128, 1);

    // Q projection; K, V projections skip masked-out rows
    gemm_h1<<<gproj, blk, GEMM_SMEM>>>(P.seqh, P.wqh, ND, 0, 0,
        5, 1.f, bq, nullptr, 0, ND, P.qh, nullptr, 0);
    gemm_h1<<<gproj, blk, GEMM_SMEM>>>(P.seqh, P.wkh, ND, 0, 0,
        5, 1.f, bk, nullptr, 0, ND, P.kh, lens, 3);
    gemm_h1<<<gproj, blk, GEMM_SMEM>>>(P.seqh, P.wvh, ND, 0, 0,
        6, 1.f, bv, nullptr, 0, ND, P.vth, lens, 3);

    // scores = Q K^T / 32 (masked n-tiles skipped)
    gemm_h1<<<dim3(NS / 128, NS / 128, NB), blk, GEMM_SMEM>>>(
        P.qh, P.kh, ND, SD, SD,
        0, 1.0f / 32.0f, nullptr, P.sc, SS2, NS, nullptr, lens, 1);

    softmax_rows<<<dim3(NS, NB), 256>>>(P.sc, P.sch, lens);

    // attn = P @ V (B-operand = V^T, K truncated at len)
    gemm_h1<<<dim3(ND / 128, NS / 128, NB), blk, GEMM_SMEM>>>(
        P.sch, P.vth, NS, SS2, SD,
        0, 1.f, nullptr, P.attn, SD, ND, nullptr, lens, 2);

    // post = LN(seq + attn) -> fp16 only (A-operand AND residual for FFN)
    add_ln<<<NB * NS, 256>>>(P.attn, seq, g1, b1, nullptr, P.posth);

    // ffn = relu(post @ Wo^T + bo) + post(fp16)
    gemm_h1<<<gproj, blk, GEMM_SMEM>>>(P.posth, P.woh, ND, 0, 0,
        4, 1.f, bo, P.ffn, 0, ND, P.posth, nullptr, 0);

    // out = LN(ffn)
    add_ln<<<NB * NS, 256>>>(P.ffn, nullptr, g2, b2, out, nullptr);
}